// round 3
// baseline (speedup 1.0000x reference)
#include <cuda_runtime.h>
#include <math.h>
#include <stdint.h>

#define B 64
#define S 2048
#define E 1024
#define H 512
#define EMB 256
#define V 50257
#define BS (B*S)

// ---------------- device scratch (no allocations allowed) ----------------
__device__ float g_energy[BS];        // energy -> attn (in place)
__device__ float g_ws_app[B*H];
__device__ float g_context[B*E];
__device__ float g_embed[B*EMB];
__device__ float g_gates[B*4*H];
__device__ float g_ht[B*H];
__device__ float g_ct[B*H];
__device__ float g_logits[(size_t)B*V];
__device__ float g_pgen[B];

// ---------------- helpers ----------------
__device__ __forceinline__ float sigmoidf_(float x){ return 1.f/(1.f+expf(-x)); }

__device__ __forceinline__ uint32_t f2tf32(float f){
  uint32_t u; asm("cvt.rna.tf32.f32 %0, %1;" : "=r"(u) : "f"(f)); return u;
}
// 3xTF32 split: x = hi + lo with hi = tf32(x), lo = tf32(x - hi).
__device__ __forceinline__ void split3(float f, uint32_t& hi, uint32_t& lo){
  uint32_t h; asm("cvt.rna.tf32.f32 %0, %1;" : "=r"(h) : "f"(f));
  float r = f - __uint_as_float(h);
  uint32_t l; asm("cvt.rna.tf32.f32 %0, %1;" : "=r"(l) : "f"(r));
  hi = h; lo = l;
}
__device__ __forceinline__ void mma_tf32(float* c, const uint32_t* a, uint32_t b0, uint32_t b1){
  asm volatile("mma.sync.aligned.m16n8k8.row.col.f32.tf32.tf32.f32 "
    "{%0,%1,%2,%3}, {%4,%5,%6,%7}, {%8,%9}, {%0,%1,%2,%3};"
    : "+f"(c[0]),"+f"(c[1]),"+f"(c[2]),"+f"(c[3])
    : "r"(a[0]),"r"(a[1]),"r"(a[2]),"r"(a[3]),"r"(b0),"r"(b1));
}

// ---------------- kernels ----------------
__global__ void zero_kernel(){
  int i = blockIdx.x*blockDim.x + threadIdx.x;
  int stride = gridDim.x*blockDim.x;
  for (int j=i;j<BS;j+=stride)     g_energy[j]=0.f;
  for (int j=i;j<B*E;j+=stride)    g_context[j]=0.f;
  for (int j=i;j<B*4*H;j+=stride)  g_gates[j]=0.f;
}

// ws_app[b,h] = h0[b]·attn_ws_w[h] + attn_ws_b[h]
__global__ void ws_app_kernel(const float* __restrict__ h0,
                              const float* __restrict__ wsw,
                              const float* __restrict__ wsb){
  int b = blockIdx.x;
  __shared__ float hs[H];
  for (int k=threadIdx.x;k<H;k+=blockDim.x) hs[k]=h0[b*H+k];
  __syncthreads();
  for (int h=threadIdx.x; h<H; h+=blockDim.x){
    const float4* wr = (const float4*)&wsw[(size_t)h*H];
    float s=0.f;
    #pragma unroll 4
    for (int k=0;k<H/4;k++){
      float4 w = wr[k];
      s += w.x*hs[4*k] + w.y*hs[4*k+1] + w.z*hs[4*k+2] + w.w*hs[4*k+3];
    }
    g_ws_app[b*H+h] = s + wsb[h];
  }
}

__global__ void embed_kernel(const int* __restrict__ dec_input, const float* __restrict__ table){
  int b=blockIdx.x;
  int tok = dec_input[b];
  g_embed[b*EMB + threadIdx.x] = table[(size_t)tok*EMB + threadIdx.x];
}

// energy[b,s] += sum over 128-col tile of attn_v[h]*tanh(enc[b,s]·whw[h] + whb[h] + ws_app[b,h])
// GEMM M=131072, N=512, K=1024, 3xTF32 mma, block tile 128x128, kb=16, 8 warps (4x2)
// hi/lo splits precomputed into smem once per k-chunk; next chunk prefetched into regs.
// grid: (col=4 fastest, row=1024) so the 4 col-blocks of a row tile share enc via L2.
__global__ __launch_bounds__(256) void energy_gemm_kernel(
    const float* __restrict__ enc, const float* __restrict__ whw,
    const float* __restrict__ whb, const float* __restrict__ attn_v)
{
  __shared__ uint32_t Ah[128][20];
  __shared__ uint32_t Al[128][20];
  __shared__ uint32_t Bh[128][20];
  __shared__ uint32_t Bl[128][20];
  __shared__ float red[128];
  const int tid=threadIdx.x, lane=tid&31, wid=tid>>5;
  const int col0 = blockIdx.x*128;
  const int row0 = blockIdx.y*128;
  const int warpM = wid>>1, warpN = wid&1;     // 4 x 2 warps, warp tile 32x64
  float acc[2][8][4];
  #pragma unroll
  for (int a=0;a<2;a++)
    #pragma unroll
    for(int n=0;n<8;n++)
      #pragma unroll
      for(int c=0;c<4;c++) acc[a][n][c]=0.f;

  // prefetch registers: per k-chunk each thread handles 2 float4 of A and 2 of B
  const int pr0 = (tid    )>>2, pc0 = ((tid    )&3)*4;
  const int pr1 = (tid+256)>>2, pc1 = ((tid+256)&3)*4;
  float4 pa0, pa1, pb0, pb1;

  pa0 = *(const float4*)&enc[(size_t)(row0+pr0)*E + pc0];
  pa1 = *(const float4*)&enc[(size_t)(row0+pr1)*E + pc1];
  pb0 = *(const float4*)&whw[(size_t)(col0+pr0)*E + pc0];
  pb1 = *(const float4*)&whw[(size_t)(col0+pr1)*E + pc1];

  for (int k0=0;k0<E;k0+=16){
    // split current chunk into smem
    {
      uint32_t h,l;
      split3(pa0.x,h,l); Ah[pr0][pc0  ]=h; Al[pr0][pc0  ]=l;
      split3(pa0.y,h,l); Ah[pr0][pc0+1]=h; Al[pr0][pc0+1]=l;
      split3(pa0.z,h,l); Ah[pr0][pc0+2]=h; Al[pr0][pc0+2]=l;
      split3(pa0.w,h,l); Ah[pr0][pc0+3]=h; Al[pr0][pc0+3]=l;
      split3(pa1.x,h,l); Ah[pr1][pc1  ]=h; Al[pr1][pc1  ]=l;
      split3(pa1.y,h,l); Ah[pr1][pc1+1]=h; Al[pr1][pc1+1]=l;
      split3(pa1.z,h,l); Ah[pr1][pc1+2]=h; Al[pr1][pc1+2]=l;
      split3(pa1.w,h,l); Ah[pr1][pc1+3]=h; Al[pr1][pc1+3]=l;
      split3(pb0.x,h,l); Bh[pr0][pc0  ]=h; Bl[pr0][pc0  ]=l;
      split3(pb0.y,h,l); Bh[pr0][pc0+1]=h; Bl[pr0][pc0+1]=l;
      split3(pb0.z,h,l); Bh[pr0][pc0+2]=h; Bl[pr0][pc0+2]=l;
      split3(pb0.w,h,l); Bh[pr0][pc0+3]=h; Bl[pr0][pc0+3]=l;
      split3(pb1.x,h,l); Bh[pr1][pc1  ]=h; Bl[pr1][pc1  ]=l;
      split3(pb1.y,h,l); Bh[pr1][pc1+1]=h; Bl[pr1][pc1+1]=l;
      split3(pb1.z,h,l); Bh[pr1][pc1+2]=h; Bl[pr1][pc1+2]=l;
      split3(pb1.w,h,l); Bh[pr1][pc1+3]=h; Bl[pr1][pc1+3]=l;
    }
    __syncthreads();
    // prefetch next chunk (overlaps with MMA compute below)
    if (k0+16 < E){
      int kn = k0+16;
      pa0 = *(const float4*)&enc[(size_t)(row0+pr0)*E + kn + pc0];
      pa1 = *(const float4*)&enc[(size_t)(row0+pr1)*E + kn + pc1];
      pb0 = *(const float4*)&whw[(size_t)(col0+pr0)*E + kn + pc0];
      pb1 = *(const float4*)&whw[(size_t)(col0+pr1)*E + kn + pc1];
    }
    #pragma unroll
    for (int ks=0;ks<16;ks+=8){
      uint32_t ah[2][4], al[2][4];
      int ar = warpM*32 + (lane>>2);
      int ac = ks + (lane&3);
      #pragma unroll
      for (int mf=0;mf<2;mf++){
        int r = ar + mf*16;
        ah[mf][0]=Ah[r  ][ac  ]; al[mf][0]=Al[r  ][ac  ];
        ah[mf][1]=Ah[r+8][ac  ]; al[mf][1]=Al[r+8][ac  ];
        ah[mf][2]=Ah[r  ][ac+4]; al[mf][2]=Al[r  ][ac+4];
        ah[mf][3]=Ah[r+8][ac+4]; al[mf][3]=Al[r+8][ac+4];
      }
      #pragma unroll
      for (int nf=0;nf<8;nf++){
        int bn_ = warpN*64 + nf*8 + (lane>>2);
        int bk  = ks + (lane&3);
        uint32_t bh0=Bh[bn_][bk  ], bl0=Bl[bn_][bk  ];
        uint32_t bh1=Bh[bn_][bk+4], bl1=Bl[bn_][bk+4];
        mma_tf32(acc[0][nf], ah[0], bh0, bh1);
        mma_tf32(acc[0][nf], ah[0], bl0, bl1);
        mma_tf32(acc[0][nf], al[0], bh0, bh1);
        mma_tf32(acc[1][nf], ah[1], bh0, bh1);
        mma_tf32(acc[1][nf], ah[1], bl0, bl1);
        mma_tf32(acc[1][nf], al[1], bh0, bh1);
      }
    }
    __syncthreads();
  }

  if (tid<128) red[tid]=0.f;
  __syncthreads();
  const int b = row0 >> 11;   // 2048 rows per batch, 128 | 2048
  #pragma unroll
  for (int mf=0;mf<2;mf++){
    #pragma unroll
    for (int half=0; half<2; half++){
      float sum=0.f;
      #pragma unroll
      for (int nf=0;nf<8;nf++){
        #pragma unroll
        for (int cc=0;cc<2;cc++){
          int cidx = half*2 + cc;
          int h = col0 + warpN*64 + nf*8 + 2*(lane&3) + cc;
          float z = acc[mf][nf][cidx] + whb[h] + g_ws_app[b*H + h];
          sum += attn_v[h]*tanhf(z);
        }
      }
      int rl = warpM*32 + mf*16 + (lane>>2) + half*8;
      atomicAdd(&red[rl], sum);
    }
  }
  __syncthreads();
  if (tid<128) atomicAdd(&g_energy[row0+tid], red[tid]);
}

__global__ void attn_softmax_kernel(){
  int b = blockIdx.x;
  __shared__ float sm[256];
  float m=-1e30f;
  for (int s=threadIdx.x;s<S;s+=256) m=fmaxf(m,g_energy[b*S+s]);
  sm[threadIdx.x]=m; __syncthreads();
  for (int o=128;o>0;o>>=1){ if(threadIdx.x<o) sm[threadIdx.x]=fmaxf(sm[threadIdx.x],sm[threadIdx.x+o]); __syncthreads(); }
  m = sm[0]; __syncthreads();
  float sum=0.f;
  for (int s=threadIdx.x;s<S;s+=256) sum+=expf(g_energy[b*S+s]-m);
  sm[threadIdx.x]=sum; __syncthreads();
  for (int o=128;o>0;o>>=1){ if(threadIdx.x<o) sm[threadIdx.x]+=sm[threadIdx.x+o]; __syncthreads(); }
  float inv = 1.f/sm[0];
  for (int s=threadIdx.x;s<S;s+=256) g_energy[b*S+s]=expf(g_energy[b*S+s]-m)*inv;
}

// context[b,e] += sum_{s in chunk} attn[b,s]*enc[b,s,e]
__global__ void context_kernel(const float* __restrict__ enc){
  int b = blockIdx.x;
  int s0 = blockIdx.y*128;
  __shared__ float at[128];
  for (int i=threadIdx.x;i<128;i+=256) at[i]=g_energy[b*S+s0+i];
  __syncthreads();
  float acc[4]={0.f,0.f,0.f,0.f};
  const float* base = enc + ((size_t)b*S + s0)*E;
  for (int s=0;s<128;s++){
    float a = at[s];
    const float* row = base + (size_t)s*E;
    #pragma unroll
    for (int j=0;j<4;j++) acc[j] += a*row[threadIdx.x + j*256];
  }
  #pragma unroll
  for (int j=0;j<4;j++) atomicAdd(&g_context[b*E + threadIdx.x + j*256], acc[j]);
}

// gates[b,n] += x[b]·Wih[n] + h0[b]·Whh[n], K=1792 split into 8 chunks of 224
__global__ void gates_kernel(const float* __restrict__ wih, const float* __restrict__ whh,
                             const float* __restrict__ h0){
  __shared__ float Xs[64][33];
  __shared__ float Ws[64][33];
  int tid=threadIdx.x;
  int n0 = blockIdx.x*64;
  int k0 = blockIdx.y*224;
  float acc[4][4];
  #pragma unroll
  for(int i=0;i<4;i++)
    #pragma unroll
    for(int j=0;j<4;j++) acc[i][j]=0.f;
  int tr = tid>>4, tc = tid&15;
  for (int kk=0;kk<224;kk+=32){
    int kb = k0+kk;
    #pragma unroll
    for (int i=0;i<8;i++){
      int idx = tid + i*256;
      int r = idx>>5, k = idx&31;
      int kg = kb+k;
      float x;
      if (kg<E) x = g_context[r*E+kg];
      else if (kg<E+EMB) x = g_embed[r*EMB + kg-E];
      else x = h0[r*H + kg-(E+EMB)];
      Xs[r][k]=x;
      float w = (kg<E+EMB) ? wih[(size_t)(n0+r)*(E+EMB) + kg]
                           : whh[(size_t)(n0+r)*H + (kg-(E+EMB))];
      Ws[r][k]=w;
    }
    __syncthreads();
    #pragma unroll
    for (int k=0;k<32;k++){
      float xv[4],wv[4];
      #pragma unroll
      for(int i=0;i<4;i++) xv[i]=Xs[tr*4+i][k];
      #pragma unroll
      for(int j=0;j<4;j++) wv[j]=Ws[tc*4+j][k];
      #pragma unroll
      for(int i=0;i<4;i++)
        #pragma unroll
        for(int j=0;j<4;j++) acc[i][j]+=xv[i]*wv[j];
    }
    __syncthreads();
  }
  #pragma unroll
  for(int i=0;i<4;i++)
    #pragma unroll
    for(int j=0;j<4;j++)
      atomicAdd(&g_gates[(tr*4+i)*(4*H) + n0 + tc*4 + j], acc[i][j]);
}

__global__ void lstm_kernel(const float* __restrict__ c0,
                            const float* __restrict__ b_ih, const float* __restrict__ b_hh,
                            float* __restrict__ out){
  int b=blockIdx.x, h=threadIdx.x;
  const float* g = &g_gates[b*4*H];
  float ig = g[h]       + b_ih[h]       + b_hh[h];
  float fg = g[H+h]     + b_ih[H+h]     + b_hh[H+h];
  float gg = g[2*H+h]   + b_ih[2*H+h]   + b_hh[2*H+h];
  float og = g[3*H+h]   + b_ih[3*H+h]   + b_hh[3*H+h];
  float c  = sigmoidf_(fg)*c0[b*H+h] + sigmoidf_(ig)*tanhf(gg);
  float ht = sigmoidf_(og)*tanhf(c);
  g_ht[b*H+h]=ht; g_ct[b*H+h]=c;
  out[(size_t)B*V + b*H + h] = ht;
  out[(size_t)B*V + (size_t)B*H + b*H + h] = c;
}

// logits[b,n] = ht[b]·vw[n] + vb[n], M=64 N=50257 K=512, 2-term split tf32, tile 64x128
__global__ __launch_bounds__(256) void logits_gemm_kernel(const float* __restrict__ vw,
                                                          const float* __restrict__ vb){
  __shared__ float As[64][36];
  __shared__ float Bs[128][36];
  const int tid=threadIdx.x, lane=tid&31, wid=tid>>5;
  const int col0 = blockIdx.x*128;
  const int warpM = wid>>2, warpN = wid&3;    // 2 x 4 warps, warp tile 32x32
  float acc[2][4][4];
  #pragma unroll
  for (int a=0;a<2;a++)
    #pragma unroll
    for(int n=0;n<4;n++)
      #pragma unroll
      for(int c=0;c<4;c++) acc[a][n][c]=0.f;

  for (int k0=0;k0<H;k0+=32){
    #pragma unroll
    for (int i=0;i<2;i++){
      int idx = tid + i*256;
      int r = idx>>3, c=(idx&7)*4;
      *(float4*)&As[r][c] = *(const float4*)&g_ht[r*H + k0 + c];
    }
    #pragma unroll
    for (int i=0;i<4;i++){
      int idx = tid + i*256;
      int r = idx>>3, c=(idx&7)*4;
      int n = col0 + r;
      float4 v = (n<V) ? *(const float4*)&vw[(size_t)n*H + k0 + c] : make_float4(0.f,0.f,0.f,0.f);
      *(float4*)&Bs[r][c] = v;
    }
    __syncthreads();
    #pragma unroll
    for (int ks=0;ks<32;ks+=8){
      uint32_t ah[2][4], al[2][4];
      int ar = warpM*32 + (lane>>2);
      int ac = ks + (lane&3);
      #pragma unroll
      for (int mf=0;mf<2;mf++){
        int r = ar + mf*16;
        split3(As[r  ][ac  ], ah[mf][0], al[mf][0]);
        split3(As[r+8][ac  ], ah[mf][1], al[mf][1]);
        split3(As[r  ][ac+4], ah[mf][2], al[mf][2]);
        split3(As[r+8][ac+4], ah[mf][3], al[mf][3]);
      }
      #pragma unroll
      for (int nf=0;nf<4;nf++){
        int bn_ = warpN*32 + nf*8 + (lane>>2);
        int bk  = ks + (lane&3);
        uint32_t bh0,bl0,bh1,bl1;
        split3(Bs[bn_][bk  ], bh0, bl0);
        split3(Bs[bn_][bk+4], bh1, bl1);
        // 2.5-term: hi*hi + hi*lo + lo*hi(dropped) -> keep hi*hi, hi*blo, alo*bh
        mma_tf32(acc[0][nf], ah[0], bh0, bh1);
        mma_tf32(acc[0][nf], ah[0], bl0, bl1);
        mma_tf32(acc[1][nf], ah[1], bh0, bh1);
        mma_tf32(acc[1][nf], ah[1], bl0, bl1);
        mma_tf32(acc[0][nf], al[0], bh0, bh1);
        mma_tf32(acc[1][nf], al[1], bh0, bh1);
      }
    }
    __syncthreads();
  }
  #pragma unroll
  for (int mf=0;mf<2;mf++)
    #pragma unroll
    for (int nf=0;nf<4;nf++)
      #pragma unroll
      for (int cidx=0;cidx<4;cidx++){
        int r = warpM*32 + mf*16 + (lane>>2) + (cidx>>1)*8;
        int n = col0 + warpN*32 + nf*8 + 2*(lane&3) + (cidx&1);
        if (n<V) g_logits[(size_t)r*V + n] = acc[mf][nf][cidx] + vb[n];
      }
}

__global__ void pgen_kernel(const float* __restrict__ whv, const float* __restrict__ wsv,
                            const float* __restrict__ wxv){
  int b=blockIdx.x;
  __shared__ float sm[256];
  float s=0.f;
  for (int e=threadIdx.x;e<E;e+=256) s+=g_context[b*E+e]*whv[e];
  for (int h=threadIdx.x;h<H;h+=256) s+=g_ht[b*H+h]*wsv[h];
  if (threadIdx.x<EMB) s+=g_embed[b*EMB+threadIdx.x]*wxv[threadIdx.x];
  sm[threadIdx.x]=s; __syncthreads();
  for (int o=128;o>0;o>>=1){ if(threadIdx.x<o) sm[threadIdx.x]+=sm[threadIdx.x+o]; __syncthreads(); }
  if (threadIdx.x==0) g_pgen[b]=1.f/(1.f+expf(-sm[0]));
}

__global__ void vocab_out_kernel(float* __restrict__ out){
  int b=blockIdx.x;
  __shared__ float sm[256];
  const float* l = &g_logits[(size_t)b*V];
  float m=-1e30f;
  for (int v=threadIdx.x;v<V;v+=256) m=fmaxf(m,l[v]);
  sm[threadIdx.x]=m; __syncthreads();
  for (int o=128;o>0;o>>=1){ if(threadIdx.x<o) sm[threadIdx.x]=fmaxf(sm[threadIdx.x],sm[threadIdx.x+o]); __syncthreads(); }
  m=sm[0]; __syncthreads();
  float s=0.f;
  for (int v=threadIdx.x;v<V;v+=256) s+=expf(l[v]-m);
  sm[threadIdx.x]=s; __syncthreads();
  for (int o=128;o>0;o>>=1){ if(threadIdx.x<o) sm[threadIdx.x]+=sm[threadIdx.x+o]; __syncthreads(); }
  float scale = g_pgen[b]/sm[0];
  for (int v=threadIdx.x;v<V;v+=256) out[(size_t)b*V+v]=expf(l[v]-m)*scale;
}

__global__ void scatter_kernel(const int* __restrict__ enc_inputs, float* __restrict__ out){
  int b=blockIdx.x;
  float om = 1.f - g_pgen[b];
  for (int s=threadIdx.x;s<S;s+=256){
    int tok = enc_inputs[b*S+s];
    atomicAdd(&out[(size_t)b*V+tok], om*g_energy[b*S+s]);
  }
}

// ---------------- launch ----------------
extern "C" void kernel_launch(void* const* d_in, const int* in_sizes, int n_in,
                              void* d_out, int out_size){
  const float* enc_out     = (const float*)d_in[0];
  const float* h0          = (const float*)d_in[1];
  const float* c0          = (const float*)d_in[2];
  const int*   dec_input   = (const int*)  d_in[3];
  const int*   enc_inputs  = (const int*)  d_in[4];
  const float* embed_table = (const float*)d_in[5];
  const float* attn_wh_w   = (const float*)d_in[6];
  const float* attn_wh_b   = (const float*)d_in[7];
  const float* attn_ws_w   = (const float*)d_in[8];
  const float* attn_ws_b   = (const float*)d_in[9];
  const float* attn_v      = (const float*)d_in[10];
  const float* lstm_w_ih   = (const float*)d_in[11];
  const float* lstm_w_hh   = (const float*)d_in[12];
  const float* lstm_b_ih   = (const float*)d_in[13];
  const float* lstm_b_hh   = (const float*)d_in[14];
  const float* wh_vec      = (const float*)d_in[15];
  const float* ws_vec      = (const float*)d_in[16];
  const float* wx_vec      = (const float*)d_in[17];
  const float* v_w         = (const float*)d_in[18];
  const float* v_b         = (const float*)d_in[19];
  float* out = (float*)d_out;

  zero_kernel<<<256,256>>>();
  ws_app_kernel<<<B,256>>>(h0, attn_ws_w, attn_ws_b);
  embed_kernel<<<B,256>>>(dec_input, embed_table);
  energy_gemm_kernel<<<dim3(H/128, BS/128),256>>>(enc_out, attn_wh_w, attn_wh_b, attn_v);
  attn_softmax_kernel<<<B,256>>>();
  context_kernel<<<dim3(B,16),256>>>(enc_out);
  gates_kernel<<<dim3(32,8),256>>>(lstm_w_ih, lstm_w_hh, h0);
  lstm_kernel<<<B,H>>>(c0, lstm_b_ih, lstm_b_hh, out);
  logits_gemm_kernel<<<(V+127)/128,256>>>(v_w, v_b);
  pgen_kernel<<<B,256>>>(wh_vec, ws_vec, wx_vec);
  vocab_out_kernel<<<B,256>>>(out);
  scatter_kernel<<<B,256>>>(enc_inputs, out);
}

// round 4
// speedup vs baseline: 1.2765x; 1.2765x over previous
#include <cuda_runtime.h>
#include <math.h>
#include <stdint.h>

#define B 64
#define S 2048
#define E 1024
#define H 512
#define EMB 256
#define V 50257
#define BS (B*S)

// ---------------- device scratch (no allocations allowed) ----------------
__device__ float g_energy[BS];        // energy -> attn (in place)
__device__ float g_ws_app[B*H];
__device__ float g_context[B*E];
__device__ float g_embed[B*EMB];
__device__ float g_gates[B*4*H];
__device__ float g_ht[B*H];
__device__ float g_ct[B*H];
__device__ float g_logits[(size_t)B*V];
__device__ float g_pgen[B];

// ---------------- helpers ----------------
__device__ __forceinline__ float sigmoidf_(float x){ return 1.f/(1.f+expf(-x)); }

__device__ __forceinline__ uint32_t f2tf32(float f){
  uint32_t u; asm("cvt.rna.tf32.f32 %0, %1;" : "=r"(u) : "f"(f)); return u;
}
// 3xTF32 split: x = hi + lo with hi = tf32(x), lo = tf32(x - hi).
__device__ __forceinline__ void split3(float f, uint32_t& hi, uint32_t& lo){
  uint32_t h; asm("cvt.rna.tf32.f32 %0, %1;" : "=r"(h) : "f"(f));
  float r = f - __uint_as_float(h);
  uint32_t l; asm("cvt.rna.tf32.f32 %0, %1;" : "=r"(l) : "f"(r));
  hi = h; lo = l;
}
__device__ __forceinline__ void mma_tf32(float* c, const uint32_t* a, uint32_t b0, uint32_t b1){
  asm volatile("mma.sync.aligned.m16n8k8.row.col.f32.tf32.tf32.f32 "
    "{%0,%1,%2,%3}, {%4,%5,%6,%7}, {%8,%9}, {%0,%1,%2,%3};"
    : "+f"(c[0]),"+f"(c[1]),"+f"(c[2]),"+f"(c[3])
    : "r"(a[0]),"r"(a[1]),"r"(a[2]),"r"(a[3]),"r"(b0),"r"(b1));
}
__device__ __forceinline__ uint32_t smem_u32(const void* p){
  return (uint32_t)__cvta_generic_to_shared(p);
}
__device__ __forceinline__ void cp8(uint32_t s, const float* g){
  asm volatile("cp.async.ca.shared.global [%0], [%1], 8;" :: "r"(s), "l"(g));
}

// ---------------- kernels ----------------
__global__ void zero_kernel(){
  int i = blockIdx.x*blockDim.x + threadIdx.x;
  int stride = gridDim.x*blockDim.x;
  for (int j=i;j<BS;j+=stride)     g_energy[j]=0.f;
  for (int j=i;j<B*E;j+=stride)    g_context[j]=0.f;
  for (int j=i;j<B*4*H;j+=stride)  g_gates[j]=0.f;
}

// ws_app[b,h] = h0[b]·attn_ws_w[h] + attn_ws_b[h]
__global__ void ws_app_kernel(const float* __restrict__ h0,
                              const float* __restrict__ wsw,
                              const float* __restrict__ wsb){
  int b = blockIdx.x;
  __shared__ float hs[H];
  for (int k=threadIdx.x;k<H;k+=blockDim.x) hs[k]=h0[b*H+k];
  __syncthreads();
  for (int h=threadIdx.x; h<H; h+=blockDim.x){
    const float4* wr = (const float4*)&wsw[(size_t)h*H];
    float s=0.f;
    #pragma unroll 4
    for (int k=0;k<H/4;k++){
      float4 w = wr[k];
      s += w.x*hs[4*k] + w.y*hs[4*k+1] + w.z*hs[4*k+2] + w.w*hs[4*k+3];
    }
    g_ws_app[b*H+h] = s + wsb[h];
  }
}

__global__ void embed_kernel(const int* __restrict__ dec_input, const float* __restrict__ table){
  int b=blockIdx.x;
  int tok = dec_input[b];
  g_embed[b*EMB + threadIdx.x] = table[(size_t)tok*EMB + threadIdx.x];
}

// energy[b,s] += sum over 128-col tile of attn_v[h]*tanh(enc[b,s]·whw[h] + whb[h] + ws_app[b,h])
// GEMM M=131072, N=512, K=1024, 3xTF32 mma, block tile 128x128, kb=16,
// 2-stage cp.async double buffer, fp32 smem tiles, splits in registers.
// grid: (col=4 fastest, row=1024) so col-blocks of a row tile share enc via L2.
__global__ __launch_bounds__(256) void energy_gemm_kernel(
    const float* __restrict__ enc, const float* __restrict__ whw,
    const float* __restrict__ whb, const float* __restrict__ attn_v)
{
  __shared__ float As[2][128][18];
  __shared__ float Bs[2][128][18];
  __shared__ float red[128];
  const int tid=threadIdx.x, lane=tid&31, wid=tid>>5;
  const int col0 = blockIdx.x*128;
  const int row0 = blockIdx.y*128;
  const int warpM = wid>>1, warpN = wid&1;     // 4 x 2 warps, warp tile 32x64
  float acc[2][8][4];
  #pragma unroll
  for (int a=0;a<2;a++)
    #pragma unroll
    for(int n=0;n<8;n++)
      #pragma unroll
      for(int c=0;c<4;c++) acc[a][n][c]=0.f;

  uint32_t a_sm[2], b_sm[2];
  a_sm[0]=smem_u32(&As[0][0][0]); a_sm[1]=smem_u32(&As[1][0][0]);
  b_sm[0]=smem_u32(&Bs[0][0][0]); b_sm[1]=smem_u32(&Bs[1][0][0]);

  // issue one stage of async copies: 128 rows x 16 floats per array, 8B chunks
  auto issue = [&](int stage, int k0){
    #pragma unroll
    for (int i=0;i<4;i++){
      int ci = i*256 + tid;
      int r = ci>>3, c=(ci&7)*2;
      cp8(a_sm[stage] + (uint32_t)(r*18+c)*4, &enc[(size_t)(row0+r)*E + k0 + c]);
      cp8(b_sm[stage] + (uint32_t)(r*18+c)*4, &whw[(size_t)(col0+r)*E + k0 + c]);
    }
    asm volatile("cp.async.commit_group;" ::: "memory");
  };

  issue(0, 0);
  const int NCHUNK = E/16;
  for (int chunk=0; chunk<NCHUNK; chunk++){
    int stage = chunk&1;
    if (chunk+1 < NCHUNK){
      issue(stage^1, (chunk+1)*16);
      asm volatile("cp.async.wait_group 1;" ::: "memory");
    } else {
      asm volatile("cp.async.wait_group 0;" ::: "memory");
    }
    __syncthreads();
    #pragma unroll
    for (int ks=0;ks<16;ks+=8){
      uint32_t ah[2][4], al[2][4];
      int ar = warpM*32 + (lane>>2);
      int ac = ks + (lane&3);
      #pragma unroll
      for (int mf=0;mf<2;mf++){
        int r = ar + mf*16;
        split3(As[stage][r  ][ac  ], ah[mf][0], al[mf][0]);
        split3(As[stage][r+8][ac  ], ah[mf][1], al[mf][1]);
        split3(As[stage][r  ][ac+4], ah[mf][2], al[mf][2]);
        split3(As[stage][r+8][ac+4], ah[mf][3], al[mf][3]);
      }
      #pragma unroll
      for (int nf=0;nf<8;nf++){
        int bn_ = warpN*64 + nf*8 + (lane>>2);
        int bk  = ks + (lane&3);
        uint32_t bh0,bl0,bh1,bl1;
        split3(Bs[stage][bn_][bk  ], bh0, bl0);
        split3(Bs[stage][bn_][bk+4], bh1, bl1);
        mma_tf32(acc[0][nf], ah[0], bh0, bh1);
        mma_tf32(acc[0][nf], ah[0], bl0, bl1);
        mma_tf32(acc[0][nf], al[0], bh0, bh1);
        mma_tf32(acc[1][nf], ah[1], bh0, bh1);
        mma_tf32(acc[1][nf], ah[1], bl0, bl1);
        mma_tf32(acc[1][nf], al[1], bh0, bh1);
      }
    }
    __syncthreads();
  }

  if (tid<128) red[tid]=0.f;
  __syncthreads();
  const int b = row0 >> 11;   // 2048 rows per batch, 128 | 2048
  #pragma unroll
  for (int mf=0;mf<2;mf++){
    #pragma unroll
    for (int half=0; half<2; half++){
      float sum=0.f;
      #pragma unroll
      for (int nf=0;nf<8;nf++){
        #pragma unroll
        for (int cc=0;cc<2;cc++){
          int cidx = half*2 + cc;
          int h = col0 + warpN*64 + nf*8 + 2*(lane&3) + cc;
          float z = acc[mf][nf][cidx] + whb[h] + g_ws_app[b*H + h];
          sum += attn_v[h]*tanhf(z);
        }
      }
      int rl = warpM*32 + mf*16 + (lane>>2) + half*8;
      atomicAdd(&red[rl], sum);
    }
  }
  __syncthreads();
  if (tid<128) atomicAdd(&g_energy[row0+tid], red[tid]);
}

__global__ void attn_softmax_kernel(){
  int b = blockIdx.x;
  __shared__ float sm[256];
  float m=-1e30f;
  for (int s=threadIdx.x;s<S;s+=256) m=fmaxf(m,g_energy[b*S+s]);
  sm[threadIdx.x]=m; __syncthreads();
  for (int o=128;o>0;o>>=1){ if(threadIdx.x<o) sm[threadIdx.x]=fmaxf(sm[threadIdx.x],sm[threadIdx.x+o]); __syncthreads(); }
  m = sm[0]; __syncthreads();
  float sum=0.f;
  for (int s=threadIdx.x;s<S;s+=256) sum+=expf(g_energy[b*S+s]-m);
  sm[threadIdx.x]=sum; __syncthreads();
  for (int o=128;o>0;o>>=1){ if(threadIdx.x<o) sm[threadIdx.x]+=sm[threadIdx.x+o]; __syncthreads(); }
  float inv = 1.f/sm[0];
  for (int s=threadIdx.x;s<S;s+=256) g_energy[b*S+s]=expf(g_energy[b*S+s]-m)*inv;
}

// context[b,e] += sum_{s in chunk} attn[b,s]*enc[b,s,e]
__global__ void context_kernel(const float* __restrict__ enc){
  int b = blockIdx.x;
  int s0 = blockIdx.y*128;
  __shared__ float at[128];
  for (int i=threadIdx.x;i<128;i+=256) at[i]=g_energy[b*S+s0+i];
  __syncthreads();
  float acc[4]={0.f,0.f,0.f,0.f};
  const float* base = enc + ((size_t)b*S + s0)*E;
  for (int s=0;s<128;s++){
    float a = at[s];
    const float* row = base + (size_t)s*E;
    #pragma unroll
    for (int j=0;j<4;j++) acc[j] += a*row[threadIdx.x + j*256];
  }
  #pragma unroll
  for (int j=0;j<4;j++) atomicAdd(&g_context[b*E + threadIdx.x + j*256], acc[j]);
}

// gates[b,n] += x[b]·Wih[n] + h0[b]·Whh[n], K=1792 split into 8 chunks of 224
__global__ void gates_kernel(const float* __restrict__ wih, const float* __restrict__ whh,
                             const float* __restrict__ h0){
  __shared__ float Xs[64][33];
  __shared__ float Ws[64][33];
  int tid=threadIdx.x;
  int n0 = blockIdx.x*64;
  int k0 = blockIdx.y*224;
  float acc[4][4];
  #pragma unroll
  for(int i=0;i<4;i++)
    #pragma unroll
    for(int j=0;j<4;j++) acc[i][j]=0.f;
  int tr = tid>>4, tc = tid&15;
  for (int kk=0;kk<224;kk+=32){
    int kb = k0+kk;
    #pragma unroll
    for (int i=0;i<8;i++){
      int idx = tid + i*256;
      int r = idx>>5, k = idx&31;
      int kg = kb+k;
      float x;
      if (kg<E) x = g_context[r*E+kg];
      else if (kg<E+EMB) x = g_embed[r*EMB + kg-E];
      else x = h0[r*H + kg-(E+EMB)];
      Xs[r][k]=x;
      float w = (kg<E+EMB) ? wih[(size_t)(n0+r)*(E+EMB) + kg]
                           : whh[(size_t)(n0+r)*H + (kg-(E+EMB))];
      Ws[r][k]=w;
    }
    __syncthreads();
    #pragma unroll
    for (int k=0;k<32;k++){
      float xv[4],wv[4];
      #pragma unroll
      for(int i=0;i<4;i++) xv[i]=Xs[tr*4+i][k];
      #pragma unroll
      for(int j=0;j<4;j++) wv[j]=Ws[tc*4+j][k];
      #pragma unroll
      for(int i=0;i<4;i++)
        #pragma unroll
        for(int j=0;j<4;j++) acc[i][j]+=xv[i]*wv[j];
    }
    __syncthreads();
  }
  #pragma unroll
  for(int i=0;i<4;i++)
    #pragma unroll
    for(int j=0;j<4;j++)
      atomicAdd(&g_gates[(tr*4+i)*(4*H) + n0 + tc*4 + j], acc[i][j]);
}

__global__ void lstm_kernel(const float* __restrict__ c0,
                            const float* __restrict__ b_ih, const float* __restrict__ b_hh,
                            float* __restrict__ out){
  int b=blockIdx.x, h=threadIdx.x;
  const float* g = &g_gates[b*4*H];
  float ig = g[h]       + b_ih[h]       + b_hh[h];
  float fg = g[H+h]     + b_ih[H+h]     + b_hh[H+h];
  float gg = g[2*H+h]   + b_ih[2*H+h]   + b_hh[2*H+h];
  float og = g[3*H+h]   + b_ih[3*H+h]   + b_hh[3*H+h];
  float c  = sigmoidf_(fg)*c0[b*H+h] + sigmoidf_(ig)*tanhf(gg);
  float ht = sigmoidf_(og)*tanhf(c);
  g_ht[b*H+h]=ht; g_ct[b*H+h]=c;
  out[(size_t)B*V + b*H + h] = ht;
  out[(size_t)B*V + (size_t)B*H + b*H + h] = c;
}

// logits[b,n] = ht[b]·vw[n] + vb[n], M=64 N=50257 K=512, 3xTF32, tile 64x128
__global__ __launch_bounds__(256) void logits_gemm_kernel(const float* __restrict__ vw,
                                                          const float* __restrict__ vb){
  __shared__ float As[64][36];
  __shared__ float Bs[128][36];
  const int tid=threadIdx.x, lane=tid&31, wid=tid>>5;
  const int col0 = blockIdx.x*128;
  const int warpM = wid>>2, warpN = wid&3;    // 2 x 4 warps, warp tile 32x32
  float acc[2][4][4];
  #pragma unroll
  for (int a=0;a<2;a++)
    #pragma unroll
    for(int n=0;n<4;n++)
      #pragma unroll
      for(int c=0;c<4;c++) acc[a][n][c]=0.f;

  for (int k0=0;k0<H;k0+=32){
    #pragma unroll
    for (int i=0;i<2;i++){
      int idx = tid + i*256;
      int r = idx>>3, c=(idx&7)*4;
      *(float4*)&As[r][c] = *(const float4*)&g_ht[r*H + k0 + c];
    }
    #pragma unroll
    for (int i=0;i<4;i++){
      int idx = tid + i*256;
      int r = idx>>3, c=(idx&7)*4;
      int n = col0 + r;
      float4 v = (n<V) ? *(const float4*)&vw[(size_t)n*H + k0 + c] : make_float4(0.f,0.f,0.f,0.f);
      *(float4*)&Bs[r][c] = v;
    }
    __syncthreads();
    #pragma unroll
    for (int ks=0;ks<32;ks+=8){
      uint32_t ah[2][4], al[2][4];
      int ar = warpM*32 + (lane>>2);
      int ac = ks + (lane&3);
      #pragma unroll
      for (int mf=0;mf<2;mf++){
        int r = ar + mf*16;
        split3(As[r  ][ac  ], ah[mf][0], al[mf][0]);
        split3(As[r+8][ac  ], ah[mf][1], al[mf][1]);
        split3(As[r  ][ac+4], ah[mf][2], al[mf][2]);
        split3(As[r+8][ac+4], ah[mf][3], al[mf][3]);
      }
      #pragma unroll
      for (int nf=0;nf<4;nf++){
        int bn_ = warpN*32 + nf*8 + (lane>>2);
        int bk  = ks + (lane&3);
        uint32_t bh0,bl0,bh1,bl1;
        split3(Bs[bn_][bk  ], bh0, bl0);
        split3(Bs[bn_][bk+4], bh1, bl1);
        mma_tf32(acc[0][nf], ah[0], bh0, bh1);
        mma_tf32(acc[0][nf], ah[0], bl0, bl1);
        mma_tf32(acc[0][nf], al[0], bh0, bh1);
        mma_tf32(acc[1][nf], ah[1], bh0, bh1);
        mma_tf32(acc[1][nf], ah[1], bl0, bl1);
        mma_tf32(acc[1][nf], al[1], bh0, bh1);
      }
    }
    __syncthreads();
  }
  #pragma unroll
  for (int mf=0;mf<2;mf++)
    #pragma unroll
    for (int nf=0;nf<4;nf++)
      #pragma unroll
      for (int cidx=0;cidx<4;cidx++){
        int r = warpM*32 + mf*16 + (lane>>2) + (cidx>>1)*8;
        int n = col0 + warpN*32 + nf*8 + 2*(lane&3) + (cidx&1);
        if (n<V) g_logits[(size_t)r*V + n] = acc[mf][nf][cidx] + vb[n];
      }
}

__global__ void pgen_kernel(const float* __restrict__ whv, const float* __restrict__ wsv,
                            const float* __restrict__ wxv){
  int b=blockIdx.x;
  __shared__ float sm[256];
  float s=0.f;
  for (int e=threadIdx.x;e<E;e+=256) s+=g_context[b*E+e]*whv[e];
  for (int h=threadIdx.x;h<H;h+=256) s+=g_ht[b*H+h]*wsv[h];
  if (threadIdx.x<EMB) s+=g_embed[b*EMB+threadIdx.x]*wxv[threadIdx.x];
  sm[threadIdx.x]=s; __syncthreads();
  for (int o=128;o>0;o>>=1){ if(threadIdx.x<o) sm[threadIdx.x]+=sm[threadIdx.x+o]; __syncthreads(); }
  if (threadIdx.x==0) g_pgen[b]=1.f/(1.f+expf(-sm[0]));
}

__global__ void vocab_out_kernel(float* __restrict__ out){
  int b=blockIdx.x;
  __shared__ float sm[256];
  const float* l = &g_logits[(size_t)b*V];
  float m=-1e30f;
  for (int v=threadIdx.x;v<V;v+=256) m=fmaxf(m,l[v]);
  sm[threadIdx.x]=m; __syncthreads();
  for (int o=128;o>0;o>>=1){ if(threadIdx.x<o) sm[threadIdx.x]=fmaxf(sm[threadIdx.x],sm[threadIdx.x+o]); __syncthreads(); }
  m=sm[0]; __syncthreads();
  float s=0.f;
  for (int v=threadIdx.x;v<V;v+=256) s+=expf(l[v]-m);
  sm[threadIdx.x]=s; __syncthreads();
  for (int o=128;o>0;o>>=1){ if(threadIdx.x<o) sm[threadIdx.x]+=sm[threadIdx.x+o]; __syncthreads(); }
  float scale = g_pgen[b]/sm[0];
  for (int v=threadIdx.x;v<V;v+=256) out[(size_t)b*V+v]=expf(l[v]-m)*scale;
}

__global__ void scatter_kernel(const int* __restrict__ enc_inputs, float* __restrict__ out){
  int b=blockIdx.x;
  float om = 1.f - g_pgen[b];
  for (int s=threadIdx.x;s<S;s+=256){
    int tok = enc_inputs[b*S+s];
    atomicAdd(&out[(size_t)b*V+tok], om*g_energy[b*S+s]);
  }
}

// ---------------- launch ----------------
extern "C" void kernel_launch(void* const* d_in, const int* in_sizes, int n_in,
                              void* d_out, int out_size){
  const float* enc_out     = (const float*)d_in[0];
  const float* h0          = (const float*)d_in[1];
  const float* c0          = (const float*)d_in[2];
  const int*   dec_input   = (const int*)  d_in[3];
  const int*   enc_inputs  = (const int*)  d_in[4];
  const float* embed_table = (const float*)d_in[5];
  const float* attn_wh_w   = (const float*)d_in[6];
  const float* attn_wh_b   = (const float*)d_in[7];
  const float* attn_ws_w   = (const float*)d_in[8];
  const float* attn_ws_b   = (const float*)d_in[9];
  const float* attn_v      = (const float*)d_in[10];
  const float* lstm_w_ih   = (const float*)d_in[11];
  const float* lstm_w_hh   = (const float*)d_in[12];
  const float* lstm_b_ih   = (const float*)d_in[13];
  const float* lstm_b_hh   = (const float*)d_in[14];
  const float* wh_vec      = (const float*)d_in[15];
  const float* ws_vec      = (const float*)d_in[16];
  const float* wx_vec      = (const float*)d_in[17];
  const float* v_w         = (const float*)d_in[18];
  const float* v_b         = (const float*)d_in[19];
  float* out = (float*)d_out;

  zero_kernel<<<256,256>>>();
  ws_app_kernel<<<B,256>>>(h0, attn_ws_w, attn_ws_b);
  embed_kernel<<<B,256>>>(dec_input, embed_table);
  energy_gemm_kernel<<<dim3(H/128, BS/128),256>>>(enc_out, attn_wh_w, attn_wh_b, attn_v);
  attn_softmax_kernel<<<B,256>>>();
  context_kernel<<<dim3(B,16),256>>>(enc_out);
  gates_kernel<<<dim3(32,8),256>>>(lstm_w_ih, lstm_w_hh, h0);
  lstm_kernel<<<B,H>>>(c0, lstm_b_ih, lstm_b_hh, out);
  logits_gemm_kernel<<<(V+127)/128,256>>>(v_w, v_b);
  pgen_kernel<<<B,256>>>(wh_vec, ws_vec, wx_vec);
  vocab_out_kernel<<<B,256>>>(out);
  scatter_kernel<<<B,256>>>(enc_inputs, out);
}

// round 6
// speedup vs baseline: 1.9077x; 1.4945x over previous
#include <cuda_runtime.h>
#include <math.h>
#include <stdint.h>

#define B 64
#define S 2048
#define E 1024
#define H 512
#define EMB 256
#define V 50257
#define BS (B*S)

// ---------------- device scratch (no allocations allowed) ----------------
__device__ float g_energy[BS];        // energy -> attn (in place)
__device__ float g_ws_app[B*H];
__device__ float g_context[B*E];
__device__ float g_embed[B*EMB];
__device__ float g_gates[B*4*H];
__device__ float g_ht[B*H];
__device__ float g_ct[B*H];
__device__ float g_logits[(size_t)B*V];
__device__ float g_pgen[B];

// ---------------- helpers ----------------
__device__ __forceinline__ float sigmoidf_(float x){ return 1.f/(1.f+expf(-x)); }

// 2-way bf16 split of a pair of floats: hi = bf16x2(x0,x1), lo = bf16x2 of residuals.
// Packed: low 16 bits = element 0 (lower k), high 16 bits = element 1.
__device__ __forceinline__ void split_bf16x2(float x0, float x1, uint32_t& hi, uint32_t& lo){
  asm("cvt.rn.bf16x2.f32 %0, %1, %2;" : "=r"(hi) : "f"(x1), "f"(x0));
  float h0 = __uint_as_float(hi << 16);
  float h1 = __uint_as_float(hi & 0xFFFF0000u);
  float l0 = x0 - h0;
  float l1 = x1 - h1;
  asm("cvt.rn.bf16x2.f32 %0, %1, %2;" : "=r"(lo) : "f"(l1), "f"(l0));
}

__device__ __forceinline__ void mma_bf16(float* c, const uint32_t* a, uint32_t b0, uint32_t b1){
  asm volatile("mma.sync.aligned.m16n8k16.row.col.f32.bf16.bf16.f32 "
    "{%0,%1,%2,%3}, {%4,%5,%6,%7}, {%8,%9}, {%0,%1,%2,%3};"
    : "+f"(c[0]),"+f"(c[1]),"+f"(c[2]),"+f"(c[3])
    : "r"(a[0]),"r"(a[1]),"r"(a[2]),"r"(a[3]),"r"(b0),"r"(b1));
}

// ---------------- kernels ----------------
__global__ void zero_kernel(){
  int i = blockIdx.x*blockDim.x + threadIdx.x;
  int stride = gridDim.x*blockDim.x;
  for (int j=i;j<BS;j+=stride)     g_energy[j]=0.f;
  for (int j=i;j<B*E;j+=stride)    g_context[j]=0.f;
  for (int j=i;j<B*4*H;j+=stride)  g_gates[j]=0.f;
}

// ws_app[b,h] = h0[b]·attn_ws_w[h] + attn_ws_b[h]
__global__ void ws_app_kernel(const float* __restrict__ h0,
                              const float* __restrict__ wsw,
                              const float* __restrict__ wsb){
  int b = blockIdx.x;
  __shared__ float hs[H];
  for (int k=threadIdx.x;k<H;k+=blockDim.x) hs[k]=h0[b*H+k];
  __syncthreads();
  for (int h=threadIdx.x; h<H; h+=blockDim.x){
    const float4* wr = (const float4*)&wsw[(size_t)h*H];
    float s=0.f;
    #pragma unroll 4
    for (int k=0;k<H/4;k++){
      float4 w = wr[k];
      s += w.x*hs[4*k] + w.y*hs[4*k+1] + w.z*hs[4*k+2] + w.w*hs[4*k+3];
    }
    g_ws_app[b*H+h] = s + wsb[h];
  }
}

__global__ void embed_kernel(const int* __restrict__ dec_input, const float* __restrict__ table){
  int b=blockIdx.x;
  int tok = dec_input[b];
  g_embed[b*EMB + threadIdx.x] = table[(size_t)tok*EMB + threadIdx.x];
}

// energy[b,s] += sum over 128-col tile of attn_v[h]*tanh(enc[b,s]·whw[h] + whb[h] + ws_app[b,h])
// GEMM M=131072, N=512, K=1024. 2-way bf16 split, 3 products, mma m16n8k16.
// Block tile 128x128, kb=32, 8 warps (4x2), warp tile 32x64.
// smem holds (hi,lo) bf16x2 pairs interleaved as uint2; split done at fill time.
// grid: (col=4 fastest, row=1024) so col-blocks sharing an enc row-tile hit L2.
__global__ __launch_bounds__(256,1) void energy_gemm_kernel(
    const float* __restrict__ enc, const float* __restrict__ whw,
    const float* __restrict__ whb, const float* __restrict__ attn_v)
{
  __shared__ uint2 Ahl[128][18];   // [row][k-pair] pair = (hi bf16x2, lo bf16x2)
  __shared__ uint2 Bhl[128][18];
  __shared__ float red[128];
  const int tid=threadIdx.x, lane=tid&31, wid=tid>>5;
  const int col0 = blockIdx.x*128;
  const int row0 = blockIdx.y*128;
  const int warpM = wid>>1, warpN = wid&1;     // 4 x 2 warps, warp tile 32x64
  float acc[2][8][4];
  #pragma unroll
  for (int a=0;a<2;a++)
    #pragma unroll
    for(int n=0;n<8;n++)
      #pragma unroll
      for(int c=0;c<4;c++) acc[a][n][c]=0.f;

  // prefetch geometry: 4 float4 of A tile + 4 of B tile per thread (128x32 each)
  int prow[4], pc4[4];
  #pragma unroll
  for (int i=0;i<4;i++){ int ff=tid+i*256; prow[i]=ff>>3; pc4[i]=(ff&7)*4; }
  float4 pa[4], pb[4];
  #pragma unroll
  for (int i=0;i<4;i++){
    pa[i] = *(const float4*)&enc[(size_t)(row0+prow[i])*E + pc4[i]];
    pb[i] = *(const float4*)&whw[(size_t)(col0+prow[i])*E + pc4[i]];
  }

  const int NCHUNK = E/32;
  for (int chunk=0; chunk<NCHUNK; chunk++){
    // split + store current chunk (from prefetch regs)
    #pragma unroll
    for (int i=0;i<4;i++){
      int r = prow[i], p = pc4[i]>>1;   // pair index = c4/2
      uint32_t h,l;
      split_bf16x2(pa[i].x, pa[i].y, h, l); Ahl[r][p  ] = make_uint2(h,l);
      split_bf16x2(pa[i].z, pa[i].w, h, l); Ahl[r][p+1] = make_uint2(h,l);
      split_bf16x2(pb[i].x, pb[i].y, h, l); Bhl[r][p  ] = make_uint2(h,l);
      split_bf16x2(pb[i].z, pb[i].w, h, l); Bhl[r][p+1] = make_uint2(h,l);
    }
    __syncthreads();
    // prefetch next chunk (overlaps with MMA below)
    if (chunk+1 < NCHUNK){
      int kn = (chunk+1)*32;
      #pragma unroll
      for (int i=0;i<4;i++){
        pa[i] = *(const float4*)&enc[(size_t)(row0+prow[i])*E + kn + pc4[i]];
        pb[i] = *(const float4*)&whw[(size_t)(col0+prow[i])*E + kn + pc4[i]];
      }
    }
    #pragma unroll
    for (int kstep=0;kstep<2;kstep++){
      const int pb8 = kstep*8;
      uint32_t ah[2][4], al[2][4];
      int ar = warpM*32 + (lane>>2);
      int ap = pb8 + (lane&3);
      #pragma unroll
      for (int mf=0;mf<2;mf++){
        int r = ar + mf*16;
        uint2 v0 = Ahl[r  ][ap  ];
        uint2 v1 = Ahl[r+8][ap  ];
        uint2 v2 = Ahl[r  ][ap+4];
        uint2 v3 = Ahl[r+8][ap+4];
        ah[mf][0]=v0.x; al[mf][0]=v0.y;
        ah[mf][1]=v1.x; al[mf][1]=v1.y;
        ah[mf][2]=v2.x; al[mf][2]=v2.y;
        ah[mf][3]=v3.x; al[mf][3]=v3.y;
      }
      #pragma unroll
      for (int nf=0;nf<8;nf++){
        int bn_ = warpN*64 + nf*8 + (lane>>2);
        uint2 B0 = Bhl[bn_][ap  ];
        uint2 B1 = Bhl[bn_][ap+4];
        mma_bf16(acc[0][nf], ah[0], B0.x, B1.x);   // hi*hi
        mma_bf16(acc[0][nf], ah[0], B0.y, B1.y);   // hi*lo
        mma_bf16(acc[0][nf], al[0], B0.x, B1.x);   // lo*hi
        mma_bf16(acc[1][nf], ah[1], B0.x, B1.x);
        mma_bf16(acc[1][nf], ah[1], B0.y, B1.y);
        mma_bf16(acc[1][nf], al[1], B0.x, B1.x);
      }
    }
    __syncthreads();
  }

  if (tid<128) red[tid]=0.f;
  __syncthreads();
  const int b = row0 >> 11;   // 2048 rows per batch, 128 | 2048
  #pragma unroll
  for (int mf=0;mf<2;mf++){
    #pragma unroll
    for (int half=0; half<2; half++){
      float sum=0.f;
      #pragma unroll
      for (int nf=0;nf<8;nf++){
        #pragma unroll
        for (int cc=0;cc<2;cc++){
          int cidx = half*2 + cc;
          int h = col0 + warpN*64 + nf*8 + 2*(lane&3) + cc;
          float z = acc[mf][nf][cidx] + whb[h] + g_ws_app[b*H + h];
          sum += attn_v[h]*tanhf(z);
        }
      }
      int rl = warpM*32 + mf*16 + (lane>>2) + half*8;
      atomicAdd(&red[rl], sum);
    }
  }
  __syncthreads();
  if (tid<128) atomicAdd(&g_energy[row0+tid], red[tid]);
}

__global__ void attn_softmax_kernel(){
  int b = blockIdx.x;
  __shared__ float sm[256];
  float m=-1e30f;
  for (int s=threadIdx.x;s<S;s+=256) m=fmaxf(m,g_energy[b*S+s]);
  sm[threadIdx.x]=m; __syncthreads();
  for (int o=128;o>0;o>>=1){ if(threadIdx.x<o) sm[threadIdx.x]=fmaxf(sm[threadIdx.x],sm[threadIdx.x+o]); __syncthreads(); }
  m = sm[0]; __syncthreads();
  float sum=0.f;
  for (int s=threadIdx.x;s<S;s+=256) sum+=expf(g_energy[b*S+s]-m);
  sm[threadIdx.x]=sum; __syncthreads();
  for (int o=128;o>0;o>>=1){ if(threadIdx.x<o) sm[threadIdx.x]+=sm[threadIdx.x+o]; __syncthreads(); }
  float inv = 1.f/sm[0];
  for (int s=threadIdx.x;s<S;s+=256) g_energy[b*S+s]=expf(g_energy[b*S+s]-m)*inv;
}

// context[b,e] += sum_{s in chunk} attn[b,s]*enc[b,s,e]
__global__ void context_kernel(const float* __restrict__ enc){
  int b = blockIdx.x;
  int s0 = blockIdx.y*128;
  __shared__ float at[128];
  for (int i=threadIdx.x;i<128;i+=256) at[i]=g_energy[b*S+s0+i];
  __syncthreads();
  float acc[4]={0.f,0.f,0.f,0.f};
  const float* base = enc + ((size_t)b*S + s0)*E;
  for (int s=0;s<128;s++){
    float a = at[s];
    const float* row = base + (size_t)s*E;
    #pragma unroll
    for (int j=0;j<4;j++) acc[j] += a*row[threadIdx.x + j*256];
  }
  #pragma unroll
  for (int j=0;j<4;j++) atomicAdd(&g_context[b*E + threadIdx.x + j*256], acc[j]);
}

// gates[b,n] += x[b]·Wih[n] + h0[b]·Whh[n], K=1792 split into 8 chunks of 224
__global__ void gates_kernel(const float* __restrict__ wih, const float* __restrict__ whh,
                             const float* __restrict__ h0){
  __shared__ float Xs[64][33];
  __shared__ float Ws[64][33];
  int tid=threadIdx.x;
  int n0 = blockIdx.x*64;
  int k0 = blockIdx.y*224;
  float acc[4][4];
  #pragma unroll
  for(int i=0;i<4;i++)
    #pragma unroll
    for(int j=0;j<4;j++) acc[i][j]=0.f;
  int tr = tid>>4, tc = tid&15;
  for (int kk=0;kk<224;kk+=32){
    int kb = k0+kk;
    #pragma unroll
    for (int i=0;i<8;i++){
      int idx = tid + i*256;
      int r = idx>>5, k = idx&31;
      int kg = kb+k;
      float x;
      if (kg<E) x = g_context[r*E+kg];
      else if (kg<E+EMB) x = g_embed[r*EMB + kg-E];
      else x = h0[r*H + kg-(E+EMB)];
      Xs[r][k]=x;
      float w = (kg<E+EMB) ? wih[(size_t)(n0+r)*(E+EMB) + kg]
                           : whh[(size_t)(n0+r)*H + (kg-(E+EMB))];
      Ws[r][k]=w;
    }
    __syncthreads();
    #pragma unroll
    for (int k=0;k<32;k++){
      float xv[4],wv[4];
      #pragma unroll
      for(int i=0;i<4;i++) xv[i]=Xs[tr*4+i][k];
      #pragma unroll
      for(int j=0;j<4;j++) wv[j]=Ws[tc*4+j][k];
      #pragma unroll
      for(int i=0;i<4;i++)
        #pragma unroll
        for(int j=0;j<4;j++) acc[i][j]+=xv[i]*wv[j];
    }
    __syncthreads();
  }
  #pragma unroll
  for(int i=0;i<4;i++)
    #pragma unroll
    for(int j=0;j<4;j++)
      atomicAdd(&g_gates[(tr*4+i)*(4*H) + n0 + tc*4 + j], acc[i][j]);
}

__global__ void lstm_kernel(const float* __restrict__ c0,
                            const float* __restrict__ b_ih, const float* __restrict__ b_hh,
                            float* __restrict__ out){
  int b=blockIdx.x, h=threadIdx.x;
  const float* g = &g_gates[b*4*H];
  float ig = g[h]       + b_ih[h]       + b_hh[h];
  float fg = g[H+h]     + b_ih[H+h]     + b_hh[H+h];
  float gg = g[2*H+h]   + b_ih[2*H+h]   + b_hh[2*H+h];
  float og = g[3*H+h]   + b_ih[3*H+h]   + b_hh[3*H+h];
  float c  = sigmoidf_(fg)*c0[b*H+h] + sigmoidf_(ig)*tanhf(gg);
  float ht = sigmoidf_(og)*tanhf(c);
  g_ht[b*H+h]=ht; g_ct[b*H+h]=c;
  out[(size_t)B*V + b*H + h] = ht;
  out[(size_t)B*V + (size_t)B*H + b*H + h] = c;
}

// logits[b,n] = ht[b]·vw[n] + vb[n], M=64 N=50257 K=512.
// 2-way bf16 split, 3 products, m16n8k16. Tile 64x128, kb=32, 8 warps (2x4).
__global__ __launch_bounds__(256) void logits_gemm_kernel(const float* __restrict__ vw,
                                                          const float* __restrict__ vb){
  __shared__ uint2 Ahl[64][18];
  __shared__ uint2 Bhl[128][18];
  const int tid=threadIdx.x, lane=tid&31, wid=tid>>5;
  const int col0 = blockIdx.x*128;
  const int warpM = wid>>2, warpN = wid&3;    // 2 x 4 warps, warp tile 32x32
  float acc[2][4][4];
  #pragma unroll
  for (int a=0;a<2;a++)
    #pragma unroll
    for(int n=0;n<4;n++)
      #pragma unroll
      for(int c=0;c<4;c++) acc[a][n][c]=0.f;

  for (int k0=0;k0<H;k0+=32){
    // A: 64x32 floats -> 2 float4 per thread
    #pragma unroll
    for (int i=0;i<2;i++){
      int ff = tid + i*256;
      int r = ff>>3, c4 = (ff&7)*4;
      float4 v = *(const float4*)&g_ht[r*H + k0 + c4];
      uint32_t h,l;
      split_bf16x2(v.x, v.y, h, l); Ahl[r][(c4>>1)  ] = make_uint2(h,l);
      split_bf16x2(v.z, v.w, h, l); Ahl[r][(c4>>1)+1] = make_uint2(h,l);
    }
    // B: 128x32 floats -> 4 float4 per thread
    #pragma unroll
    for (int i=0;i<4;i++){
      int ff = tid + i*256;
      int r = ff>>3, c4 = (ff&7)*4;
      int n = col0 + r;
      float4 v = (n<V) ? *(const float4*)&vw[(size_t)n*H + k0 + c4]
                       : make_float4(0.f,0.f,0.f,0.f);
      uint32_t h,l;
      split_bf16x2(v.x, v.y, h, l); Bhl[r][(c4>>1)  ] = make_uint2(h,l);
      split_bf16x2(v.z, v.w, h, l); Bhl[r][(c4>>1)+1] = make_uint2(h,l);
    }
    __syncthreads();
    #pragma unroll
    for (int kstep=0;kstep<2;kstep++){
      const int pb8 = kstep*8;
      uint32_t ah[2][4], al[2][4];
      int ar = warpM*32 + (lane>>2);
      int ap = pb8 + (lane&3);
      #pragma unroll
      for (int mf=0;mf<2;mf++){
        int r = ar + mf*16;
        uint2 v0 = Ahl[r  ][ap  ];
        uint2 v1 = Ahl[r+8][ap  ];
        uint2 v2 = Ahl[r  ][ap+4];
        uint2 v3 = Ahl[r+8][ap+4];
        ah[mf][0]=v0.x; al[mf][0]=v0.y;
        ah[mf][1]=v1.x; al[mf][1]=v1.y;
        ah[mf][2]=v2.x; al[mf][2]=v2.y;
        ah[mf][3]=v3.x; al[mf][3]=v3.y;
      }
      #pragma unroll
      for (int nf=0;nf<4;nf++){
        int bn_ = warpN*32 + nf*8 + (lane>>2);
        uint2 B0 = Bhl[bn_][ap  ];
        uint2 B1 = Bhl[bn_][ap+4];
        mma_bf16(acc[0][nf], ah[0], B0.x, B1.x);
        mma_bf16(acc[0][nf], ah[0], B0.y, B1.y);
        mma_bf16(acc[0][nf], al[0], B0.x, B1.x);
        mma_bf16(acc[1][nf], ah[1], B0.x, B1.x);
        mma_bf16(acc[1][nf], ah[1], B0.y, B1.y);
        mma_bf16(acc[1][nf], al[1], B0.x, B1.x);
      }
    }
    __syncthreads();
  }
  #pragma unroll
  for (int mf=0;mf<2;mf++)
    #pragma unroll
    for (int nf=0;nf<4;nf++)
      #pragma unroll
      for (int cidx=0;cidx<4;cidx++){
        int r = warpM*32 + mf*16 + (lane>>2) + (cidx>>1)*8;
        int n = col0 + warpN*32 + nf*8 + 2*(lane&3) + (cidx&1);
        if (n<V) g_logits[(size_t)r*V + n] = acc[mf][nf][cidx] + vb[n];
      }
}

__global__ void pgen_kernel(const float* __restrict__ whv, const float* __restrict__ wsv,
                            const float* __restrict__ wxv){
  int b=blockIdx.x;
  __shared__ float sm[256];
  float s=0.f;
  for (int e=threadIdx.x;e<E;e+=256) s+=g_context[b*E+e]*whv[e];
  for (int h=threadIdx.x;h<H;h+=256) s+=g_ht[b*H+h]*wsv[h];
  if (threadIdx.x<EMB) s+=g_embed[b*EMB+threadIdx.x]*wxv[threadIdx.x];
  sm[threadIdx.x]=s; __syncthreads();
  for (int o=128;o>0;o>>=1){ if(threadIdx.x<o) sm[threadIdx.x]+=sm[threadIdx.x+o]; __syncthreads(); }
  if (threadIdx.x==0) g_pgen[b]=1.f/(1.f+expf(-sm[0]));
}

__global__ void vocab_out_kernel(float* __restrict__ out){
  int b=blockIdx.x;
  __shared__ float sm[256];
  const float* l = &g_logits[(size_t)b*V];
  float m=-1e30f;
  for (int v=threadIdx.x;v<V;v+=256) m=fmaxf(m,l[v]);
  sm[threadIdx.x]=m; __syncthreads();
  for (int o=128;o>0;o>>=1){ if(threadIdx.x<o) sm[threadIdx.x]=fmaxf(sm[threadIdx.x],sm[threadIdx.x+o]); __syncthreads(); }
  m=sm[0]; __syncthreads();
  float s=0.f;
  for (int v=threadIdx.x;v<V;v+=256) s+=expf(l[v]-m);
  sm[threadIdx.x]=s; __syncthreads();
  for (int o=128;o>0;o>>=1){ if(threadIdx.x<o) sm[threadIdx.x]+=sm[threadIdx.x+o]; __syncthreads(); }
  float scale = g_pgen[b]/sm[0];
  for (int v=threadIdx.x;v<V;v+=256) out[(size_t)b*V+v]=expf(l[v]-m)*scale;
}

__global__ void scatter_kernel(const int* __restrict__ enc_inputs, float* __restrict__ out){
  int b=blockIdx.x;
  float om = 1.f - g_pgen[b];
  for (int s=threadIdx.x;s<S;s+=256){
    int tok = enc_inputs[b*S+s];
    atomicAdd(&out[(size_t)b*V+tok], om*g_energy[b*S+s]);
  }
}

// ---------------- launch ----------------
extern "C" void kernel_launch(void* const* d_in, const int* in_sizes, int n_in,
                              void* d_out, int out_size){
  const float* enc_out     = (const float*)d_in[0];
  const float* h0          = (const float*)d_in[1];
  const float* c0          = (const float*)d_in[2];
  const int*   dec_input   = (const int*)  d_in[3];
  const int*   enc_inputs  = (const int*)  d_in[4];
  const float* embed_table = (const float*)d_in[5];
  const float* attn_wh_w   = (const float*)d_in[6];
  const float* attn_wh_b   = (const float*)d_in[7];
  const float* attn_ws_w   = (const float*)d_in[8];
  const float* attn_ws_b   = (const float*)d_in[9];
  const float* attn_v      = (const float*)d_in[10];
  const float* lstm_w_ih   = (const float*)d_in[11];
  const float* lstm_w_hh   = (const float*)d_in[12];
  const float* lstm_b_ih   = (const float*)d_in[13];
  const float* lstm_b_hh   = (const float*)d_in[14];
  const float* wh_vec      = (const float*)d_in[15];
  const float* ws_vec      = (const float*)d_in[16];
  const float* wx_vec      = (const float*)d_in[17];
  const float* v_w         = (const float*)d_in[18];
  const float* v_b         = (const float*)d_in[19];
  float* out = (float*)d_out;

  zero_kernel<<<256,256>>>();
  ws_app_kernel<<<B,256>>>(h0, attn_ws_w, attn_ws_b);
  embed_kernel<<<B,256>>>(dec_input, embed_table);
  energy_gemm_kernel<<<dim3(H/128, BS/128),256>>>(enc_out, attn_wh_w, attn_wh_b, attn_v);
  attn_softmax_kernel<<<B,256>>>();
  context_kernel<<<dim3(B,16),256>>>(enc_out);
  gates_kernel<<<dim3(32,8),256>>>(lstm_w_ih, lstm_w_hh, h0);
  lstm_kernel<<<B,H>>>(c0, lstm_b_ih, lstm_b_hh, out);
  logits_gemm_kernel<<<(V+127)/128,256>>>(v_w, v_b);
  pgen_kernel<<<B,256>>>(wh_vec, ws_vec, wx_vec);
  vocab_out_kernel<<<B,256>>>(out);
  scatter_kernel<<<B,256>>>(enc_inputs, out);
}

// round 7
// speedup vs baseline: 2.0709x; 1.0855x over previous
#include <cuda_runtime.h>
#include <math.h>
#include <stdint.h>

#define B 64
#define S 2048
#define E 1024
#define H 512
#define EMB 256
#define V 50257
#define BS (B*S)

// ---------------- device scratch (no allocations allowed) ----------------
__device__ float g_energy[BS];        // energy -> attn (in place)
__device__ float g_ws_app[B*H];
__device__ float g_context[B*E];
__device__ float g_embed[B*EMB];
__device__ float g_gates[B*4*H];
__device__ float g_ht[B*H];
__device__ float g_ct[B*H];
__device__ float g_logits[(size_t)B*V];
__device__ float g_pgen[B];
// pre-split weights: each uint4 = (hi01, lo01, hi23, lo23) bf16x2 for 4 consecutive k
__device__ uint4 g_whw2[(size_t)H*E/4];
__device__ uint4 g_vw2[(size_t)V*H/4];

// ---------------- helpers ----------------
__device__ __forceinline__ float sigmoidf_(float x){ return 1.f/(1.f+expf(-x)); }

// 2-way bf16 split of a pair of floats: hi = bf16x2(x0,x1), lo = bf16x2 of residuals.
__device__ __forceinline__ void split_bf16x2(float x0, float x1, uint32_t& hi, uint32_t& lo){
  asm("cvt.rn.bf16x2.f32 %0, %1, %2;" : "=r"(hi) : "f"(x1), "f"(x0));
  float h0 = __uint_as_float(hi << 16);
  float h1 = __uint_as_float(hi & 0xFFFF0000u);
  float l0 = x0 - h0;
  float l1 = x1 - h1;
  asm("cvt.rn.bf16x2.f32 %0, %1, %2;" : "=r"(lo) : "f"(l1), "f"(l0));
}

__device__ __forceinline__ void mma_bf16(float* c, const uint32_t* a, uint32_t b0, uint32_t b1){
  asm volatile("mma.sync.aligned.m16n8k16.row.col.f32.bf16.bf16.f32 "
    "{%0,%1,%2,%3}, {%4,%5,%6,%7}, {%8,%9}, {%0,%1,%2,%3};"
    : "+f"(c[0]),"+f"(c[1]),"+f"(c[2]),"+f"(c[3])
    : "r"(a[0]),"r"(a[1]),"r"(a[2]),"r"(a[3]),"r"(b0),"r"(b1));
}
__device__ __forceinline__ uint32_t smem_u32(const void* p){
  return (uint32_t)__cvta_generic_to_shared(p);
}
__device__ __forceinline__ void cp16(uint32_t s, const void* g){
  asm volatile("cp.async.cg.shared.global [%0], [%1], 16;" :: "r"(s), "l"(g));
}

// ---------------- kernels ----------------
__global__ void zero_kernel(){
  int i = blockIdx.x*blockDim.x + threadIdx.x;
  int stride = gridDim.x*blockDim.x;
  for (int j=i;j<BS;j+=stride)     g_energy[j]=0.f;
  for (int j=i;j<B*E;j+=stride)    g_context[j]=0.f;
  for (int j=i;j<B*4*H;j+=stride)  g_gates[j]=0.f;
}

// pre-split whw and v_w into packed (hi,lo) bf16x2 arrays
__global__ void conv_split_kernel(const float* __restrict__ whw, const float* __restrict__ vw){
  size_t i = (size_t)blockIdx.x*blockDim.x + threadIdx.x;
  size_t stride = (size_t)gridDim.x*blockDim.x;
  for (size_t j=i; j<(size_t)H*E/4; j+=stride){
    float4 v = ((const float4*)whw)[j];
    uint32_t h0,l0,h1,l1;
    split_bf16x2(v.x,v.y,h0,l0);
    split_bf16x2(v.z,v.w,h1,l1);
    g_whw2[j] = make_uint4(h0,l0,h1,l1);
  }
  for (size_t j=i; j<(size_t)V*H/4; j+=stride){
    float4 v = ((const float4*)vw)[j];
    uint32_t h0,l0,h1,l1;
    split_bf16x2(v.x,v.y,h0,l0);
    split_bf16x2(v.z,v.w,h1,l1);
    g_vw2[j] = make_uint4(h0,l0,h1,l1);
  }
}

// ws_app[b,h] = h0[b]·attn_ws_w[h] + attn_ws_b[h]
__global__ void ws_app_kernel(const float* __restrict__ h0,
                              const float* __restrict__ wsw,
                              const float* __restrict__ wsb){
  int b = blockIdx.x;
  __shared__ float hs[H];
  for (int k=threadIdx.x;k<H;k+=blockDim.x) hs[k]=h0[b*H+k];
  __syncthreads();
  for (int h=threadIdx.x; h<H; h+=blockDim.x){
    const float4* wr = (const float4*)&wsw[(size_t)h*H];
    float s=0.f;
    #pragma unroll 4
    for (int k=0;k<H/4;k++){
      float4 w = wr[k];
      s += w.x*hs[4*k] + w.y*hs[4*k+1] + w.z*hs[4*k+2] + w.w*hs[4*k+3];
    }
    g_ws_app[b*H+h] = s + wsb[h];
  }
}

__global__ void embed_kernel(const int* __restrict__ dec_input, const float* __restrict__ table){
  int b=blockIdx.x;
  int tok = dec_input[b];
  g_embed[b*EMB + threadIdx.x] = table[(size_t)tok*EMB + threadIdx.x];
}

// ---------------- energy GEMM ----------------
// energy[b,s] += sum over 256-col tile of attn_v[h]*tanh(enc[b,s]·whw[h] + whb[h] + ws_app[b,h])
// M=131072, N=512, K=1024; 2-way bf16 split, 3 products, m16n8k16.
// Block 128x256, 8 warps (2x4), warp tile 64x64, kb=32.
// B pre-split in gmem -> cp.async 16B double-buffer. A split in-kernel from prefetch regs.
// smem row stride 20 pairs (160B): conflict-free LDS.64, 16B-aligned cp.async.
#define EG_A    0u                     // [128][20] uint2 = 20480
#define EG_B    20480u                 // [2][256][20] uint2 = 81920
#define EG_RED  102400u                // 128 floats
#define EG_SMEM 102912u

__global__ void __launch_bounds__(256,1) energy_gemm_kernel(
    const float* __restrict__ enc, const float* __restrict__ whb,
    const float* __restrict__ attn_v)
{
  extern __shared__ char smem[];
  const uint32_t sbase = smem_u32(smem);
  uint2 (*Ahl)[20] = (uint2(*)[20])(smem + EG_A);
  float* red = (float*)(smem + EG_RED);
  const int tid=threadIdx.x, lane=tid&31, wid=tid>>5;
  const int col0 = blockIdx.x*256;      // h columns
  const int row0 = blockIdx.y*128;      // seq rows
  const int warpM = wid>>2, warpN = wid&3;   // 2 x 4 warps, warp tile 64x64
  float acc[4][8][4];
  #pragma unroll
  for (int a=0;a<4;a++)
    #pragma unroll
    for(int n=0;n<8;n++)
      #pragma unroll
      for(int c=0;c<4;c++) acc[a][n][c]=0.f;

  // A prefetch geometry: 4 float4 per thread of the 128x32 fp32 tile
  int prow[4], pc4[4];
  #pragma unroll
  for (int i=0;i<4;i++){ int ff=tid+i*256; prow[i]=ff>>3; pc4[i]=(ff&7)*4; }
  float4 pa[4];
  #pragma unroll
  for (int i=0;i<4;i++)
    pa[i] = *(const float4*)&enc[(size_t)(row0+prow[i])*E + pc4[i]];

  // B issue: 256 rows x 8 uint4 per chunk -> 8 cp16 per thread
  auto issueB = [&](int stage, int kq0){   // kq0 in uint4 units (chunk*8)
    #pragma unroll
    for (int i=0;i<8;i++){
      int ci = i*256 + tid;
      int r = ci>>3, c = ci&7;
      uint32_t dst = sbase + EG_B + (uint32_t)stage*40960u + (uint32_t)(r*160 + c*16);
      cp16(dst, &g_whw2[(size_t)(col0+r)*(E/4) + kq0 + c]);
    }
    asm volatile("cp.async.commit_group;" ::: "memory");
  };

  issueB(0, 0);
  const int NCHUNK = E/32;
  for (int chunk=0; chunk<NCHUNK; chunk++){
    int s = chunk&1;
    // fill A from prefetch regs (split to (hi,lo) pairs)
    #pragma unroll
    for (int i=0;i<4;i++){
      int r = prow[i], p = pc4[i]>>1;
      uint32_t h,l;
      split_bf16x2(pa[i].x, pa[i].y, h, l); Ahl[r][p  ] = make_uint2(h,l);
      split_bf16x2(pa[i].z, pa[i].w, h, l); Ahl[r][p+1] = make_uint2(h,l);
    }
    if (chunk+1 < NCHUNK){
      issueB(s^1, (chunk+1)*8);
      asm volatile("cp.async.wait_group 1;" ::: "memory");
    } else {
      asm volatile("cp.async.wait_group 0;" ::: "memory");
    }
    __syncthreads();
    // prefetch next A chunk (overlaps MMA)
    if (chunk+1 < NCHUNK){
      int kn = (chunk+1)*32;
      #pragma unroll
      for (int i=0;i<4;i++)
        pa[i] = *(const float4*)&enc[(size_t)(row0+prow[i])*E + kn + pc4[i]];
    }
    uint2 (*Bhl)[20] = (uint2(*)[20])(smem + EG_B + (uint32_t)s*40960u);
    #pragma unroll
    for (int kstep=0;kstep<2;kstep++){
      int ap = kstep*8 + (lane&3);
      uint32_t ah[4][4], al[4][4];
      int arb = warpM*64 + (lane>>2);
      #pragma unroll
      for (int mf=0;mf<4;mf++){
        int r = arb + mf*16;
        uint2 v0 = Ahl[r  ][ap  ];
        uint2 v1 = Ahl[r+8][ap  ];
        uint2 v2 = Ahl[r  ][ap+4];
        uint2 v3 = Ahl[r+8][ap+4];
        ah[mf][0]=v0.x; al[mf][0]=v0.y;
        ah[mf][1]=v1.x; al[mf][1]=v1.y;
        ah[mf][2]=v2.x; al[mf][2]=v2.y;
        ah[mf][3]=v3.x; al[mf][3]=v3.y;
      }
      #pragma unroll
      for (int nf=0;nf<8;nf++){
        int bn_ = warpN*64 + nf*8 + (lane>>2);
        uint2 B0 = Bhl[bn_][ap  ];
        uint2 B1 = Bhl[bn_][ap+4];
        #pragma unroll
        for (int mf=0;mf<4;mf++){
          mma_bf16(acc[mf][nf], ah[mf], B0.x, B1.x);   // hi*hi
          mma_bf16(acc[mf][nf], ah[mf], B0.y, B1.y);   // hi*lo
          mma_bf16(acc[mf][nf], al[mf], B0.x, B1.x);   // lo*hi
        }
      }
    }
    __syncthreads();
  }

  if (tid<128) red[tid]=0.f;
  __syncthreads();
  const int b = row0 >> 11;   // 2048 rows per batch
  #pragma unroll
  for (int mf=0;mf<4;mf++){
    #pragma unroll
    for (int half=0; half<2; half++){
      float sum=0.f;
      #pragma unroll
      for (int nf=0;nf<8;nf++){
        #pragma unroll
        for (int cc=0;cc<2;cc++){
          int cidx = half*2 + cc;
          int h = col0 + warpN*64 + nf*8 + 2*(lane&3) + cc;
          float z = acc[mf][nf][cidx] + whb[h] + g_ws_app[b*H + h];
          sum += attn_v[h]*tanhf(z);
        }
      }
      int rl = warpM*64 + mf*16 + (lane>>2) + half*8;
      atomicAdd(&red[rl], sum);
    }
  }
  __syncthreads();
  if (tid<128) atomicAdd(&g_energy[row0+tid], red[tid]);
}

__global__ void attn_softmax_kernel(){
  int b = blockIdx.x;
  __shared__ float sm[256];
  float m=-1e30f;
  for (int s=threadIdx.x;s<S;s+=256) m=fmaxf(m,g_energy[b*S+s]);
  sm[threadIdx.x]=m; __syncthreads();
  for (int o=128;o>0;o>>=1){ if(threadIdx.x<o) sm[threadIdx.x]=fmaxf(sm[threadIdx.x],sm[threadIdx.x+o]); __syncthreads(); }
  m = sm[0]; __syncthreads();
  float sum=0.f;
  for (int s=threadIdx.x;s<S;s+=256) sum+=expf(g_energy[b*S+s]-m);
  sm[threadIdx.x]=sum; __syncthreads();
  for (int o=128;o>0;o>>=1){ if(threadIdx.x<o) sm[threadIdx.x]+=sm[threadIdx.x+o]; __syncthreads(); }
  float inv = 1.f/sm[0];
  for (int s=threadIdx.x;s<S;s+=256) g_energy[b*S+s]=expf(g_energy[b*S+s]-m)*inv;
}

// context[b,e] += sum_{s in chunk} attn[b,s]*enc[b,s,e]
__global__ void context_kernel(const float* __restrict__ enc){
  int b = blockIdx.x;
  int s0 = blockIdx.y*128;
  __shared__ float at[128];
  for (int i=threadIdx.x;i<128;i+=256) at[i]=g_energy[b*S+s0+i];
  __syncthreads();
  float acc[4]={0.f,0.f,0.f,0.f};
  const float* base = enc + ((size_t)b*S + s0)*E;
  for (int s=0;s<128;s++){
    float a = at[s];
    const float* row = base + (size_t)s*E;
    #pragma unroll
    for (int j=0;j<4;j++) acc[j] += a*row[threadIdx.x + j*256];
  }
  #pragma unroll
  for (int j=0;j<4;j++) atomicAdd(&g_context[b*E + threadIdx.x + j*256], acc[j]);
}

// gates[b,n] += x[b]·Wih[n] + h0[b]·Whh[n], K=1792 split into 8 chunks of 224
__global__ void gates_kernel(const float* __restrict__ wih, const float* __restrict__ whh,
                             const float* __restrict__ h0){
  __shared__ float Xs[64][33];
  __shared__ float Ws[64][33];
  int tid=threadIdx.x;
  int n0 = blockIdx.x*64;
  int k0 = blockIdx.y*224;
  float acc[4][4];
  #pragma unroll
  for(int i=0;i<4;i++)
    #pragma unroll
    for(int j=0;j<4;j++) acc[i][j]=0.f;
  int tr = tid>>4, tc = tid&15;
  for (int kk=0;kk<224;kk+=32){
    int kb = k0+kk;
    #pragma unroll
    for (int i=0;i<8;i++){
      int idx = tid + i*256;
      int r = idx>>5, k = idx&31;
      int kg = kb+k;
      float x;
      if (kg<E) x = g_context[r*E+kg];
      else if (kg<E+EMB) x = g_embed[r*EMB + kg-E];
      else x = h0[r*H + kg-(E+EMB)];
      Xs[r][k]=x;
      float w = (kg<E+EMB) ? wih[(size_t)(n0+r)*(E+EMB) + kg]
                           : whh[(size_t)(n0+r)*H + (kg-(E+EMB))];
      Ws[r][k]=w;
    }
    __syncthreads();
    #pragma unroll
    for (int k=0;k<32;k++){
      float xv[4],wv[4];
      #pragma unroll
      for(int i=0;i<4;i++) xv[i]=Xs[tr*4+i][k];
      #pragma unroll
      for(int j=0;j<4;j++) wv[j]=Ws[tc*4+j][k];
      #pragma unroll
      for(int i=0;i<4;i++)
        #pragma unroll
        for(int j=0;j<4;j++) acc[i][j]+=xv[i]*wv[j];
    }
    __syncthreads();
  }
  #pragma unroll
  for(int i=0;i<4;i++)
    #pragma unroll
    for(int j=0;j<4;j++)
      atomicAdd(&g_gates[(tr*4+i)*(4*H) + n0 + tc*4 + j], acc[i][j]);
}

__global__ void lstm_kernel(const float* __restrict__ c0,
                            const float* __restrict__ b_ih, const float* __restrict__ b_hh,
                            float* __restrict__ out){
  int b=blockIdx.x, h=threadIdx.x;
  const float* g = &g_gates[b*4*H];
  float ig = g[h]       + b_ih[h]       + b_hh[h];
  float fg = g[H+h]     + b_ih[H+h]     + b_hh[H+h];
  float gg = g[2*H+h]   + b_ih[2*H+h]   + b_hh[2*H+h];
  float og = g[3*H+h]   + b_ih[3*H+h]   + b_hh[3*H+h];
  float c  = sigmoidf_(fg)*c0[b*H+h] + sigmoidf_(ig)*tanhf(gg);
  float ht = sigmoidf_(og)*tanhf(c);
  g_ht[b*H+h]=ht; g_ct[b*H+h]=c;
  out[(size_t)B*V + b*H + h] = ht;
  out[(size_t)B*V + (size_t)B*H + b*H + h] = c;
}

// logits[b,n] = ht[b]·vw[n] + vb[n], M=64 N=50257 K=512.
// 2-way bf16 split, 3 products, m16n8k16. Tile 64x128, kb=32, 8 warps (2x4).
// B pre-split in gmem (g_vw2); A split in-kernel.
__global__ __launch_bounds__(256) void logits_gemm_kernel(const float* __restrict__ vb){
  __shared__ uint2 Ahl[64][18];
  __shared__ uint2 Bhl[128][18];
  const int tid=threadIdx.x, lane=tid&31, wid=tid>>5;
  const int col0 = blockIdx.x*128;
  const int warpM = wid>>2, warpN = wid&3;    // 2 x 4 warps, warp tile 32x32
  float acc[2][4][4];
  #pragma unroll
  for (int a=0;a<2;a++)
    #pragma unroll
    for(int n=0;n<4;n++)
      #pragma unroll
      for(int c=0;c<4;c++) acc[a][n][c]=0.f;

  for (int k0=0;k0<H;k0+=32){
    // A: 64x32 floats -> 2 float4 per thread, split to pairs
    #pragma unroll
    for (int i=0;i<2;i++){
      int ff = tid + i*256;
      int r = ff>>3, c4 = (ff&7)*4;
      float4 v = *(const float4*)&g_ht[r*H + k0 + c4];
      uint32_t h,l;
      split_bf16x2(v.x, v.y, h, l); Ahl[r][(c4>>1)  ] = make_uint2(h,l);
      split_bf16x2(v.z, v.w, h, l); Ahl[r][(c4>>1)+1] = make_uint2(h,l);
    }
    // B: pre-split, 128 rows x 8 uint4 per chunk -> 4 uint4 loads per thread
    int kq0 = k0>>2;   // uint4 units
    #pragma unroll
    for (int i=0;i<4;i++){
      int ff = tid + i*256;
      int r = ff>>3, c = ff&7;
      int n = col0 + r;
      uint4 v = (n<V) ? g_vw2[(size_t)n*(H/4) + kq0 + c] : make_uint4(0,0,0,0);
      Bhl[r][2*c  ] = make_uint2(v.x, v.y);
      Bhl[r][2*c+1] = make_uint2(v.z, v.w);
    }
    __syncthreads();
    #pragma unroll
    for (int kstep=0;kstep<2;kstep++){
      int ap = kstep*8 + (lane&3);
      uint32_t ah[2][4], al[2][4];
      int ar = warpM*32 + (lane>>2);
      #pragma unroll
      for (int mf=0;mf<2;mf++){
        int r = ar + mf*16;
        uint2 v0 = Ahl[r  ][ap  ];
        uint2 v1 = Ahl[r+8][ap  ];
        uint2 v2 = Ahl[r  ][ap+4];
        uint2 v3 = Ahl[r+8][ap+4];
        ah[mf][0]=v0.x; al[mf][0]=v0.y;
        ah[mf][1]=v1.x; al[mf][1]=v1.y;
        ah[mf][2]=v2.x; al[mf][2]=v2.y;
        ah[mf][3]=v3.x; al[mf][3]=v3.y;
      }
      #pragma unroll
      for (int nf=0;nf<4;nf++){
        int bn_ = warpN*32 + nf*8 + (lane>>2);
        uint2 B0 = Bhl[bn_][ap  ];
        uint2 B1 = Bhl[bn_][ap+4];
        mma_bf16(acc[0][nf], ah[0], B0.x, B1.x);
        mma_bf16(acc[0][nf], ah[0], B0.y, B1.y);
        mma_bf16(acc[0][nf], al[0], B0.x, B1.x);
        mma_bf16(acc[1][nf], ah[1], B0.x, B1.x);
        mma_bf16(acc[1][nf], ah[1], B0.y, B1.y);
        mma_bf16(acc[1][nf], al[1], B0.x, B1.x);
      }
    }
    __syncthreads();
  }
  #pragma unroll
  for (int mf=0;mf<2;mf++)
    #pragma unroll
    for (int nf=0;nf<4;nf++)
      #pragma unroll
      for (int cidx=0;cidx<4;cidx++){
        int r = warpM*32 + mf*16 + (lane>>2) + (cidx>>1)*8;
        int n = col0 + warpN*32 + nf*8 + 2*(lane&3) + (cidx&1);
        if (n<V) g_logits[(size_t)r*V + n] = acc[mf][nf][cidx] + vb[n];
      }
}

__global__ void pgen_kernel(const float* __restrict__ whv, const float* __restrict__ wsv,
                            const float* __restrict__ wxv){
  int b=blockIdx.x;
  __shared__ float sm[256];
  float s=0.f;
  for (int e=threadIdx.x;e<E;e+=256) s+=g_context[b*E+e]*whv[e];
  for (int h=threadIdx.x;h<H;h+=256) s+=g_ht[b*H+h]*wsv[h];
  if (threadIdx.x<EMB) s+=g_embed[b*EMB+threadIdx.x]*wxv[threadIdx.x];
  sm[threadIdx.x]=s; __syncthreads();
  for (int o=128;o>0;o>>=1){ if(threadIdx.x<o) sm[threadIdx.x]+=sm[threadIdx.x+o]; __syncthreads(); }
  if (threadIdx.x==0) g_pgen[b]=1.f/(1.f+expf(-sm[0]));
}

__global__ void vocab_out_kernel(float* __restrict__ out){
  int b=blockIdx.x;
  __shared__ float sm[256];
  const float* l = &g_logits[(size_t)b*V];
  float m=-1e30f;
  for (int v=threadIdx.x;v<V;v+=256) m=fmaxf(m,l[v]);
  sm[threadIdx.x]=m; __syncthreads();
  for (int o=128;o>0;o>>=1){ if(threadIdx.x<o) sm[threadIdx.x]=fmaxf(sm[threadIdx.x],sm[threadIdx.x+o]); __syncthreads(); }
  m=sm[0]; __syncthreads();
  float s=0.f;
  for (int v=threadIdx.x;v<V;v+=256) s+=expf(l[v]-m);
  sm[threadIdx.x]=s; __syncthreads();
  for (int o=128;o>0;o>>=1){ if(threadIdx.x<o) sm[threadIdx.x]+=sm[threadIdx.x+o]; __syncthreads(); }
  float scale = g_pgen[b]/sm[0];
  for (int v=threadIdx.x;v<V;v+=256) out[(size_t)b*V+v]=expf(l[v]-m)*scale;
}

__global__ void scatter_kernel(const int* __restrict__ enc_inputs, float* __restrict__ out){
  int b=blockIdx.x;
  float om = 1.f - g_pgen[b];
  for (int s=threadIdx.x;s<S;s+=256){
    int tok = enc_inputs[b*S+s];
    atomicAdd(&out[(size_t)b*V+tok], om*g_energy[b*S+s]);
  }
}

// ---------------- launch ----------------
extern "C" void kernel_launch(void* const* d_in, const int* in_sizes, int n_in,
                              void* d_out, int out_size){
  const float* enc_out     = (const float*)d_in[0];
  const float* h0          = (const float*)d_in[1];
  const float* c0          = (const float*)d_in[2];
  const int*   dec_input   = (const int*)  d_in[3];
  const int*   enc_inputs  = (const int*)  d_in[4];
  const float* embed_table = (const float*)d_in[5];
  const float* attn_wh_w   = (const float*)d_in[6];
  const float* attn_wh_b   = (const float*)d_in[7];
  const float* attn_ws_w   = (const float*)d_in[8];
  const float* attn_ws_b   = (const float*)d_in[9];
  const float* attn_v      = (const float*)d_in[10];
  const float* lstm_w_ih   = (const float*)d_in[11];
  const float* lstm_w_hh   = (const float*)d_in[12];
  const float* lstm_b_ih   = (const float*)d_in[13];
  const float* lstm_b_hh   = (const float*)d_in[14];
  const float* wh_vec      = (const float*)d_in[15];
  const float* ws_vec      = (const float*)d_in[16];
  const float* wx_vec      = (const float*)d_in[17];
  const float* v_w         = (const float*)d_in[18];
  const float* v_b         = (const float*)d_in[19];
  float* out = (float*)d_out;

  // host-side attribute set (not a stream op; capture-safe)
  (void)cudaFuncSetAttribute(energy_gemm_kernel,
      cudaFuncAttributeMaxDynamicSharedMemorySize, EG_SMEM);

  zero_kernel<<<256,256>>>();
  conv_split_kernel<<<512,256>>>(attn_wh_w, v_w);
  ws_app_kernel<<<B,256>>>(h0, attn_ws_w, attn_ws_b);
  embed_kernel<<<B,256>>>(dec_input, embed_table);
  energy_gemm_kernel<<<dim3(H/256, BS/128),256,EG_SMEM>>>(enc_out, attn_wh_b, attn_v);
  attn_softmax_kernel<<<B,256>>>();
  context_kernel<<<dim3(B,16),256>>>(enc_out);
  gates_kernel<<<dim3(32,8),256>>>(lstm_w_ih, lstm_w_hh, h0);
  lstm_kernel<<<B,H>>>(c0, lstm_b_ih, lstm_b_hh, out);
  logits_gemm_kernel<<<(V+127)/128,256>>>(v_b);
  pgen_kernel<<<B,256>>>(wh_vec, ws_vec, wx_vec);
  vocab_out_kernel<<<B,256>>>(out);
  scatter_kernel<<<B,256>>>(enc_inputs, out);
}

// round 8
// speedup vs baseline: 2.1540x; 1.0401x over previous
#include <cuda_runtime.h>
#include <math.h>
#include <stdint.h>

#define B 64
#define S 2048
#define E 1024
#define H 512
#define EMB 256
#define V 50257
#define BS (B*S)

// ---------------- device scratch (no allocations allowed) ----------------
__device__ float g_energy[BS];        // attn weights (written by softmax)
__device__ float g_epart[2*BS];       // energy partials per col-block
__device__ float g_ws_app[B*H];
__device__ float g_context[B*E];
__device__ float g_embed[B*EMB];
__device__ float g_gates[B*4*H];
__device__ float g_ht[B*H];
__device__ float g_ct[B*H];
__device__ float g_logits[(size_t)B*V];
__device__ float g_pgen[B];
// pre-split whw: each uint4 = (hi01, lo01, hi23, lo23) bf16x2 for 4 consecutive k
__device__ uint4 g_whw2[(size_t)H*E/4];

// ---------------- helpers ----------------
__device__ __forceinline__ float sigmoidf_(float x){ return 1.f/(1.f+expf(-x)); }

// 2-way bf16 split of a pair of floats: hi = bf16x2(x0,x1), lo = bf16x2 of residuals.
__device__ __forceinline__ void split_bf16x2(float x0, float x1, uint32_t& hi, uint32_t& lo){
  asm("cvt.rn.bf16x2.f32 %0, %1, %2;" : "=r"(hi) : "f"(x1), "f"(x0));
  float h0 = __uint_as_float(hi << 16);
  float h1 = __uint_as_float(hi & 0xFFFF0000u);
  float l0 = x0 - h0;
  float l1 = x1 - h1;
  asm("cvt.rn.bf16x2.f32 %0, %1, %2;" : "=r"(lo) : "f"(l1), "f"(l0));
}

__device__ __forceinline__ void mma_bf16(float* c, const uint32_t* a, uint32_t b0, uint32_t b1){
  asm volatile("mma.sync.aligned.m16n8k16.row.col.f32.bf16.bf16.f32 "
    "{%0,%1,%2,%3}, {%4,%5,%6,%7}, {%8,%9}, {%0,%1,%2,%3};"
    : "+f"(c[0]),"+f"(c[1]),"+f"(c[2]),"+f"(c[3])
    : "r"(a[0]),"r"(a[1]),"r"(a[2]),"r"(a[3]),"r"(b0),"r"(b1));
}
__device__ __forceinline__ uint32_t smem_u32(const void* p){
  return (uint32_t)__cvta_generic_to_shared(p);
}
__device__ __forceinline__ void cp16(uint32_t s, const void* g){
  asm volatile("cp.async.cg.shared.global [%0], [%1], 16;" :: "r"(s), "l"(g));
}

// ---------------- kernels ----------------
// pre-split whw only (4MB; reused by 2048 CTAs)
__global__ void conv_whw_kernel(const float* __restrict__ whw){
  size_t i = (size_t)blockIdx.x*blockDim.x + threadIdx.x;
  size_t stride = (size_t)gridDim.x*blockDim.x;
  for (size_t j=i; j<(size_t)H*E/4; j+=stride){
    float4 v = ((const float4*)whw)[j];
    uint32_t h0,l0,h1,l1;
    split_bf16x2(v.x,v.y,h0,l0);
    split_bf16x2(v.z,v.w,h1,l1);
    g_whw2[j] = make_uint4(h0,l0,h1,l1);
  }
}

// ws_app[b,h] = h0[b]·attn_ws_w[h] + attn_ws_b[h]
__global__ void ws_app_kernel(const float* __restrict__ h0,
                              const float* __restrict__ wsw,
                              const float* __restrict__ wsb){
  int b = blockIdx.x;
  __shared__ float hs[H];
  for (int k=threadIdx.x;k<H;k+=blockDim.x) hs[k]=h0[b*H+k];
  __syncthreads();
  for (int h=threadIdx.x; h<H; h+=blockDim.x){
    const float4* wr = (const float4*)&wsw[(size_t)h*H];
    float s=0.f;
    #pragma unroll 4
    for (int k=0;k<H/4;k++){
      float4 w = wr[k];
      s += w.x*hs[4*k] + w.y*hs[4*k+1] + w.z*hs[4*k+2] + w.w*hs[4*k+3];
    }
    g_ws_app[b*H+h] = s + wsb[h];
  }
}

__global__ void embed_kernel(const int* __restrict__ dec_input, const float* __restrict__ table){
  int b=blockIdx.x;
  int tok = dec_input[b];
  g_embed[b*EMB + threadIdx.x] = table[(size_t)tok*EMB + threadIdx.x];
}

// ---------------- energy GEMM ----------------
// epart[cb][b,s] = sum over 256-col tile cb of attn_v[h]*tanh(enc·whw + whb + ws_app)
// M=131072, N=512, K=1024; 2-way bf16 split, 3 products, m16n8k16.
// Block 128x256, 8 warps (2x4), warp tile 64x64, kb=32.
// A double-buffered (split+STS overlapped with MMA), B double-buffered cp.async.
#define EG_A    0u                     // [2][128][20] uint2 = 40960
#define EG_B    40960u                 // [2][256][20] uint2 = 81920
#define EG_RED  122880u                // 128 floats
#define EG_SMEM 123392u

__global__ void __launch_bounds__(256,1) energy_gemm_kernel(
    const float* __restrict__ enc, const float* __restrict__ whb,
    const float* __restrict__ attn_v)
{
  extern __shared__ char smem[];
  const uint32_t sbase = smem_u32(smem);
  float* red = (float*)(smem + EG_RED);
  const int tid=threadIdx.x, lane=tid&31, wid=tid>>5;
  const int col0 = blockIdx.x*256;      // h columns
  const int row0 = blockIdx.y*128;      // seq rows
  const int warpM = wid>>2, warpN = wid&3;   // 2 x 4 warps, warp tile 64x64
  float acc[4][8][4];
  #pragma unroll
  for (int a=0;a<4;a++)
    #pragma unroll
    for(int n=0;n<8;n++)
      #pragma unroll
      for(int c=0;c<4;c++) acc[a][n][c]=0.f;

  // A prefetch geometry: 4 float4 per thread of the 128x32 fp32 tile
  int prow[4], pc4[4];
  #pragma unroll
  for (int i=0;i<4;i++){ int ff=tid+i*256; prow[i]=ff>>3; pc4[i]=(ff&7)*4; }
  float4 pa[4];
  #pragma unroll
  for (int i=0;i<4;i++)
    pa[i] = *(const float4*)&enc[(size_t)(row0+prow[i])*E + pc4[i]];

  auto fillA = [&](int stage){
    uint2 (*A)[20] = (uint2(*)[20])(smem + EG_A + (uint32_t)stage*20480u);
    #pragma unroll
    for (int i=0;i<4;i++){
      int r = prow[i], p = pc4[i]>>1;
      uint32_t h,l;
      split_bf16x2(pa[i].x, pa[i].y, h, l); A[r][p  ] = make_uint2(h,l);
      split_bf16x2(pa[i].z, pa[i].w, h, l); A[r][p+1] = make_uint2(h,l);
    }
  };
  auto issueB = [&](int stage, int kq0){   // kq0 in uint4 units (chunk*8)
    #pragma unroll
    for (int i=0;i<8;i++){
      int ci = i*256 + tid;
      int r = ci>>3, c = ci&7;
      uint32_t dst = sbase + EG_B + (uint32_t)stage*40960u + (uint32_t)(r*160 + c*16);
      cp16(dst, &g_whw2[(size_t)(col0+r)*(E/4) + kq0 + c]);
    }
    asm volatile("cp.async.commit_group;" ::: "memory");
  };

  const int NCHUNK = E/32;
  // prologue: stage 0 = chunk 0
  issueB(0, 0);
  fillA(0);
  // prefetch A chunk 1
  #pragma unroll
  for (int i=0;i<4;i++)
    pa[i] = *(const float4*)&enc[(size_t)(row0+prow[i])*E + 32 + pc4[i]];
  asm volatile("cp.async.wait_group 0;" ::: "memory");
  __syncthreads();

  for (int chunk=0; chunk<NCHUNK; chunk++){
    int s = chunk&1;
    // loop-top (post-barrier): prepare stage s^1 for chunk+1, overlapped with MMA below
    if (chunk+1 < NCHUNK){
      issueB(s^1, (chunk+1)*8);
      fillA(s^1);
      if (chunk+2 < NCHUNK){
        int kn = (chunk+2)*32;
        #pragma unroll
        for (int i=0;i<4;i++)
          pa[i] = *(const float4*)&enc[(size_t)(row0+prow[i])*E + kn + pc4[i]];
      }
    }
    uint2 (*Ahl)[20] = (uint2(*)[20])(smem + EG_A + (uint32_t)s*20480u);
    uint2 (*Bhl)[20] = (uint2(*)[20])(smem + EG_B + (uint32_t)s*40960u);
    #pragma unroll
    for (int kstep=0;kstep<2;kstep++){
      int ap = kstep*8 + (lane&3);
      uint32_t ah[4][4], al[4][4];
      int arb = warpM*64 + (lane>>2);
      #pragma unroll
      for (int mf=0;mf<4;mf++){
        int r = arb + mf*16;
        uint2 v0 = Ahl[r  ][ap  ];
        uint2 v1 = Ahl[r+8][ap  ];
        uint2 v2 = Ahl[r  ][ap+4];
        uint2 v3 = Ahl[r+8][ap+4];
        ah[mf][0]=v0.x; al[mf][0]=v0.y;
        ah[mf][1]=v1.x; al[mf][1]=v1.y;
        ah[mf][2]=v2.x; al[mf][2]=v2.y;
        ah[mf][3]=v3.x; al[mf][3]=v3.y;
      }
      #pragma unroll
      for (int nf=0;nf<8;nf++){
        int bn_ = warpN*64 + nf*8 + (lane>>2);
        uint2 B0 = Bhl[bn_][ap  ];
        uint2 B1 = Bhl[bn_][ap+4];
        #pragma unroll
        for (int mf=0;mf<4;mf++){
          mma_bf16(acc[mf][nf], ah[mf], B0.x, B1.x);   // hi*hi
          mma_bf16(acc[mf][nf], ah[mf], B0.y, B1.y);   // hi*lo
          mma_bf16(acc[mf][nf], al[mf], B0.x, B1.x);   // lo*hi
        }
      }
    }
    if (chunk+1 < NCHUNK)
      asm volatile("cp.async.wait_group 0;" ::: "memory");
    __syncthreads();
  }

  if (tid<128) red[tid]=0.f;
  __syncthreads();
  const int b = row0 >> 11;   // 2048 rows per batch
  #pragma unroll
  for (int mf=0;mf<4;mf++){
    #pragma unroll
    for (int half=0; half<2; half++){
      float sum=0.f;
      #pragma unroll
      for (int nf=0;nf<8;nf++){
        #pragma unroll
        for (int cc=0;cc<2;cc++){
          int cidx = half*2 + cc;
          int h = col0 + warpN*64 + nf*8 + 2*(lane&3) + cc;
          float z = acc[mf][nf][cidx] + whb[h] + g_ws_app[b*H + h];
          sum += attn_v[h]*tanhf(z);
        }
      }
      int rl = warpM*64 + mf*16 + (lane>>2) + half*8;
      atomicAdd(&red[rl], sum);
    }
  }
  __syncthreads();
  if (tid<128) g_epart[blockIdx.x*BS + row0 + tid] = red[tid];
}

__global__ void zero_kernel(){
  int i = blockIdx.x*blockDim.x + threadIdx.x;
  int stride = gridDim.x*blockDim.x;
  for (int j=i;j<B*E;j+=stride)    g_context[j]=0.f;
  for (int j=i;j<B*4*H;j+=stride)  g_gates[j]=0.f;
}

__global__ void attn_softmax_kernel(){
  int b = blockIdx.x;
  __shared__ float sm[256];
  float m=-1e30f;
  for (int s=threadIdx.x;s<S;s+=256){
    float e = g_epart[b*S+s] + g_epart[BS + b*S+s];
    g_energy[b*S+s] = e;
    m=fmaxf(m,e);
  }
  sm[threadIdx.x]=m; __syncthreads();
  for (int o=128;o>0;o>>=1){ if(threadIdx.x<o) sm[threadIdx.x]=fmaxf(sm[threadIdx.x],sm[threadIdx.x+o]); __syncthreads(); }
  m = sm[0]; __syncthreads();
  float sum=0.f;
  for (int s=threadIdx.x;s<S;s+=256) sum+=expf(g_energy[b*S+s]-m);
  sm[threadIdx.x]=sum; __syncthreads();
  for (int o=128;o>0;o>>=1){ if(threadIdx.x<o) sm[threadIdx.x]+=sm[threadIdx.x+o]; __syncthreads(); }
  float inv = 1.f/sm[0];
  for (int s=threadIdx.x;s<S;s+=256) g_energy[b*S+s]=expf(g_energy[b*S+s]-m)*inv;
}

// context[b,e] += sum_{s in chunk} attn[b,s]*enc[b,s,e]
__global__ void context_kernel(const float* __restrict__ enc){
  int b = blockIdx.x;
  int s0 = blockIdx.y*128;
  __shared__ float at[128];
  for (int i=threadIdx.x;i<128;i+=256) at[i]=g_energy[b*S+s0+i];
  __syncthreads();
  float acc[4]={0.f,0.f,0.f,0.f};
  const float* base = enc + ((size_t)b*S + s0)*E;
  for (int s=0;s<128;s++){
    float a = at[s];
    const float* row = base + (size_t)s*E;
    #pragma unroll
    for (int j=0;j<4;j++) acc[j] += a*row[threadIdx.x + j*256];
  }
  #pragma unroll
  for (int j=0;j<4;j++) atomicAdd(&g_context[b*E + threadIdx.x + j*256], acc[j]);
}

// gates[b,n] += x[b]·Wih[n] + h0[b]·Whh[n], K=1792 split into 8 chunks of 224
__global__ void gates_kernel(const float* __restrict__ wih, const float* __restrict__ whh,
                             const float* __restrict__ h0){
  __shared__ float Xs[64][33];
  __shared__ float Ws[64][33];
  int tid=threadIdx.x;
  int n0 = blockIdx.x*64;
  int k0 = blockIdx.y*224;
  float acc[4][4];
  #pragma unroll
  for(int i=0;i<4;i++)
    #pragma unroll
    for(int j=0;j<4;j++) acc[i][j]=0.f;
  int tr = tid>>4, tc = tid&15;
  for (int kk=0;kk<224;kk+=32){
    int kb = k0+kk;
    #pragma unroll
    for (int i=0;i<8;i++){
      int idx = tid + i*256;
      int r = idx>>5, k = idx&31;
      int kg = kb+k;
      float x;
      if (kg<E) x = g_context[r*E+kg];
      else if (kg<E+EMB) x = g_embed[r*EMB + kg-E];
      else x = h0[r*H + kg-(E+EMB)];
      Xs[r][k]=x;
      float w = (kg<E+EMB) ? wih[(size_t)(n0+r)*(E+EMB) + kg]
                           : whh[(size_t)(n0+r)*H + (kg-(E+EMB))];
      Ws[r][k]=w;
    }
    __syncthreads();
    #pragma unroll
    for (int k=0;k<32;k++){
      float xv[4],wv[4];
      #pragma unroll
      for(int i=0;i<4;i++) xv[i]=Xs[tr*4+i][k];
      #pragma unroll
      for(int j=0;j<4;j++) wv[j]=Ws[tc*4+j][k];
      #pragma unroll
      for(int i=0;i<4;i++)
        #pragma unroll
        for(int j=0;j<4;j++) acc[i][j]+=xv[i]*wv[j];
    }
    __syncthreads();
  }
  #pragma unroll
  for(int i=0;i<4;i++)
    #pragma unroll
    for(int j=0;j<4;j++)
      atomicAdd(&g_gates[(tr*4+i)*(4*H) + n0 + tc*4 + j], acc[i][j]);
}

__global__ void lstm_kernel(const float* __restrict__ c0,
                            const float* __restrict__ b_ih, const float* __restrict__ b_hh,
                            float* __restrict__ out){
  int b=blockIdx.x, h=threadIdx.x;
  const float* g = &g_gates[b*4*H];
  float ig = g[h]       + b_ih[h]       + b_hh[h];
  float fg = g[H+h]     + b_ih[H+h]     + b_hh[H+h];
  float gg = g[2*H+h]   + b_ih[2*H+h]   + b_hh[2*H+h];
  float og = g[3*H+h]   + b_ih[3*H+h]   + b_hh[3*H+h];
  float c  = sigmoidf_(fg)*c0[b*H+h] + sigmoidf_(ig)*tanhf(gg);
  float ht = sigmoidf_(og)*tanhf(c);
  g_ht[b*H+h]=ht; g_ct[b*H+h]=c;
  out[(size_t)B*V + b*H + h] = ht;
  out[(size_t)B*V + (size_t)B*H + b*H + h] = c;
}

// logits[b,n] = ht[b]·vw[n] + vb[n], M=64 N=50257 K=512.
// 2-way bf16 split (in-kernel), 3 products, m16n8k16. Tile 64x128, kb=32, 8 warps (2x4).
__global__ __launch_bounds__(256) void logits_gemm_kernel(const float* __restrict__ vw,
                                                          const float* __restrict__ vb){
  __shared__ uint2 Ahl[64][18];
  __shared__ uint2 Bhl[128][18];
  const int tid=threadIdx.x, lane=tid&31, wid=tid>>5;
  const int col0 = blockIdx.x*128;
  const int warpM = wid>>2, warpN = wid&3;    // 2 x 4 warps, warp tile 32x32
  float acc[2][4][4];
  #pragma unroll
  for (int a=0;a<2;a++)
    #pragma unroll
    for(int n=0;n<4;n++)
      #pragma unroll
      for(int c=0;c<4;c++) acc[a][n][c]=0.f;

  for (int k0=0;k0<H;k0+=32){
    #pragma unroll
    for (int i=0;i<2;i++){
      int ff = tid + i*256;
      int r = ff>>3, c4 = (ff&7)*4;
      float4 v = *(const float4*)&g_ht[r*H + k0 + c4];
      uint32_t h,l;
      split_bf16x2(v.x, v.y, h, l); Ahl[r][(c4>>1)  ] = make_uint2(h,l);
      split_bf16x2(v.z, v.w, h, l); Ahl[r][(c4>>1)+1] = make_uint2(h,l);
    }
    #pragma unroll
    for (int i=0;i<4;i++){
      int ff = tid + i*256;
      int r = ff>>3, c4 = (ff&7)*4;
      int n = col0 + r;
      float4 v = (n<V) ? *(const float4*)&vw[(size_t)n*H + k0 + c4]
                       : make_float4(0.f,0.f,0.f,0.f);
      uint32_t h,l;
      split_bf16x2(v.x, v.y, h, l); Bhl[r][(c4>>1)  ] = make_uint2(h,l);
      split_bf16x2(v.z, v.w, h, l); Bhl[r][(c4>>1)+1] = make_uint2(h,l);
    }
    __syncthreads();
    #pragma unroll
    for (int kstep=0;kstep<2;kstep++){
      int ap = kstep*8 + (lane&3);
      uint32_t ah[2][4], al[2][4];
      int ar = warpM*32 + (lane>>2);
      #pragma unroll
      for (int mf=0;mf<2;mf++){
        int r = ar + mf*16;
        uint2 v0 = Ahl[r  ][ap  ];
        uint2 v1 = Ahl[r+8][ap  ];
        uint2 v2 = Ahl[r  ][ap+4];
        uint2 v3 = Ahl[r+8][ap+4];
        ah[mf][0]=v0.x; al[mf][0]=v0.y;
        ah[mf][1]=v1.x; al[mf][1]=v1.y;
        ah[mf][2]=v2.x; al[mf][2]=v2.y;
        ah[mf][3]=v3.x; al[mf][3]=v3.y;
      }
      #pragma unroll
      for (int nf=0;nf<4;nf++){
        int bn_ = warpN*32 + nf*8 + (lane>>2);
        uint2 B0 = Bhl[bn_][ap  ];
        uint2 B1 = Bhl[bn_][ap+4];
        mma_bf16(acc[0][nf], ah[0], B0.x, B1.x);
        mma_bf16(acc[0][nf], ah[0], B0.y, B1.y);
        mma_bf16(acc[0][nf], al[0], B0.x, B1.x);
        mma_bf16(acc[1][nf], ah[1], B0.x, B1.x);
        mma_bf16(acc[1][nf], ah[1], B0.y, B1.y);
        mma_bf16(acc[1][nf], al[1], B0.x, B1.x);
      }
    }
    __syncthreads();
  }
  #pragma unroll
  for (int mf=0;mf<2;mf++)
    #pragma unroll
    for (int nf=0;nf<4;nf++)
      #pragma unroll
      for (int cidx=0;cidx<4;cidx++){
        int r = warpM*32 + mf*16 + (lane>>2) + (cidx>>1)*8;
        int n = col0 + warpN*32 + nf*8 + 2*(lane&3) + (cidx&1);
        if (n<V) g_logits[(size_t)r*V + n] = acc[mf][nf][cidx] + vb[n];
      }
}

__global__ void pgen_kernel(const float* __restrict__ whv, const float* __restrict__ wsv,
                            const float* __restrict__ wxv){
  int b=blockIdx.x;
  __shared__ float sm[256];
  float s=0.f;
  for (int e=threadIdx.x;e<E;e+=256) s+=g_context[b*E+e]*whv[e];
  for (int h=threadIdx.x;h<H;h+=256) s+=g_ht[b*H+h]*wsv[h];
  if (threadIdx.x<EMB) s+=g_embed[b*EMB+threadIdx.x]*wxv[threadIdx.x];
  sm[threadIdx.x]=s; __syncthreads();
  for (int o=128;o>0;o>>=1){ if(threadIdx.x<o) sm[threadIdx.x]+=sm[threadIdx.x+o]; __syncthreads(); }
  if (threadIdx.x==0) g_pgen[b]=1.f/(1.f+expf(-sm[0]));
}

__global__ void vocab_out_kernel(float* __restrict__ out){
  int b=blockIdx.x;
  __shared__ float sm[256];
  const float* l = &g_logits[(size_t)b*V];
  float m=-1e30f;
  for (int v=threadIdx.x;v<V;v+=256) m=fmaxf(m,l[v]);
  sm[threadIdx.x]=m; __syncthreads();
  for (int o=128;o>0;o>>=1){ if(threadIdx.x<o) sm[threadIdx.x]=fmaxf(sm[threadIdx.x],sm[threadIdx.x+o]); __syncthreads(); }
  m=sm[0]; __syncthreads();
  float s=0.f;
  for (int v=threadIdx.x;v<V;v+=256) s+=expf(l[v]-m);
  sm[threadIdx.x]=s; __syncthreads();
  for (int o=128;o>0;o>>=1){ if(threadIdx.x<o) sm[threadIdx.x]+=sm[threadIdx.x+o]; __syncthreads(); }
  float scale = g_pgen[b]/sm[0];
  for (int v=threadIdx.x;v<V;v+=256) out[(size_t)b*V+v]=expf(l[v]-m)*scale;
}

__global__ void scatter_kernel(const int* __restrict__ enc_inputs, float* __restrict__ out){
  int b=blockIdx.x;
  float om = 1.f - g_pgen[b];
  for (int s=threadIdx.x;s<S;s+=256){
    int tok = enc_inputs[b*S+s];
    atomicAdd(&out[(size_t)b*V+tok], om*g_energy[b*S+s]);
  }
}

// ---------------- launch ----------------
extern "C" void kernel_launch(void* const* d_in, const int* in_sizes, int n_in,
                              void* d_out, int out_size){
  const float* enc_out     = (const float*)d_in[0];
  const float* h0          = (const float*)d_in[1];
  const float* c0          = (const float*)d_in[2];
  const int*   dec_input   = (const int*)  d_in[3];
  const int*   enc_inputs  = (const int*)  d_in[4];
  const float* embed_table = (const float*)d_in[5];
  const float* attn_wh_w   = (const float*)d_in[6];
  const float* attn_wh_b   = (const float*)d_in[7];
  const float* attn_ws_w   = (const float*)d_in[8];
  const float* attn_ws_b   = (const float*)d_in[9];
  const float* attn_v      = (const float*)d_in[10];
  const float* lstm_w_ih   = (const float*)d_in[11];
  const float* lstm_w_hh   = (const float*)d_in[12];
  const float* lstm_b_ih   = (const float*)d_in[13];
  const float* lstm_b_hh   = (const float*)d_in[14];
  const float* wh_vec      = (const float*)d_in[15];
  const float* ws_vec      = (const float*)d_in[16];
  const float* wx_vec      = (const float*)d_in[17];
  const float* v_w         = (const float*)d_in[18];
  const float* v_b         = (const float*)d_in[19];
  float* out = (float*)d_out;

  // host-side attribute set (not a stream op; capture-safe)
  (void)cudaFuncSetAttribute(energy_gemm_kernel,
      cudaFuncAttributeMaxDynamicSharedMemorySize, EG_SMEM);

  conv_whw_kernel<<<256,256>>>(attn_wh_w);                                        // 0
  ws_app_kernel<<<B,256>>>(h0, attn_ws_w, attn_ws_b);                             // 1
  embed_kernel<<<B,256>>>(dec_input, embed_table);                                // 2
  energy_gemm_kernel<<<dim3(H/256, BS/128),256,EG_SMEM>>>(enc_out, attn_wh_b, attn_v); // 3 (profiled)
  zero_kernel<<<256,256>>>();                                                     // 4
  attn_softmax_kernel<<<B,256>>>();                                               // 5
  context_kernel<<<dim3(B,16),256>>>(enc_out);
  gates_kernel<<<dim3(32,8),256>>>(lstm_w_ih, lstm_w_hh, h0);
  lstm_kernel<<<B,H>>>(c0, lstm_b_ih, lstm_b_hh, out);
  logits_gemm_kernel<<<(V+127)/128,256>>>(v_w, v_b);
  pgen_kernel<<<B,256>>>(wh_vec, ws_vec, wx_vec);
  vocab_out_kernel<<<B,256>>>(out);
  scatter_kernel<<<B,256>>>(enc_inputs, out);
}